// round 2
// baseline (speedup 1.0000x reference)
#include <cuda_runtime.h>
#include <cuda_bf16.h>
#include <cstdint>
#include <math_constants.h>

#define N_GRAPHS 4096
#define HIDDEN   256
#define STEPS    6
#define GATESD   1024   // 4*HIDDEN
#define XDIM     512    // 2*HIDDEN
#define CH       512    // attention chunk (nodes)

// ---------------- scratch (no allocation allowed) ----------------
__device__ float g_h[N_GRAPHS * HIDDEN];
__device__ float g_c[N_GRAPHS * HIDDEN];
__device__ float g_x[N_GRAPHS * XDIM];        // [h | r]
__device__ float g_gates[N_GRAPHS * GATESD];
__device__ float g_hdn[N_GRAPHS * HIDDEN];
__device__ float g_Wc[GATESD * XDIM];         // W_ih with W_hh folded into cols [0,256)
__device__ float g_bc[GATESD];                // b_ih + b_hh
__device__ int   g_start[N_GRAPHS];
__device__ int   g_end[N_GRAPHS];

// ---------------- init: zero h, c, segment bounds ----------------
__global__ void k_init() {
    int i = blockIdx.x * blockDim.x + threadIdx.x;   // grid covers 1,048,576
    g_h[i] = 0.f;
    g_c[i] = 0.f;
    if (i < N_GRAPHS) { g_start[i] = 0; g_end[i] = 0; }
}

// ---------------- fold weights: Wc, bc ----------------
__global__ void k_prep(const float* __restrict__ W_ih, const float* __restrict__ W_hh,
                       const float* __restrict__ b_ih, const float* __restrict__ b_hh) {
    int i = blockIdx.x * blockDim.x + threadIdx.x;   // grid covers 1024*512
    int n = i >> 9;        // /512
    int k = i & 511;
    float v = W_ih[n * XDIM + k];
    if (k < HIDDEN) v += W_hh[n * HIDDEN + k];
    g_Wc[i] = v;
    if (i < GATESD) g_bc[i] = b_ih[i] + b_hh[i];
}

// ---------------- segment boundaries (batch_indices sorted, int32!) ----------------
__global__ void k_segments(const int* __restrict__ idx, int nn) {
    int n = blockIdx.x * blockDim.x + threadIdx.x;
    if (n >= nn) return;
    int g = idx[n];
    if ((unsigned)g >= (unsigned)N_GRAPHS) return;   // defensive
    if (n == 0      || idx[n - 1] != g) g_start[g] = n;
    if (n == nn - 1 || idx[n + 1] != g) g_end[g]   = n + 1;
}

// ---------------- attention: one CTA per graph, online softmax ----------------
__global__ void __launch_bounds__(256, 4)
k_attention(const float* __restrict__ emb) {
    const int g    = blockIdx.x;
    const int t    = threadIdx.x;
    const int lane = t & 31;
    const int wid  = t >> 5;

    __shared__ float h_s[HIDDEN];
    __shared__ float R_s[HIDDEN];
    __shared__ float e_s[CH];
    __shared__ float red[32];
    __shared__ float sm_m, sm_S, sm_scale, sm_nm;

    h_s[t] = g_h[(size_t)g * HIDDEN + t];
    R_s[t] = 0.f;
    if (t == 0) { sm_m = -CUDART_INF_F; sm_S = 0.f; }
    const int s  = g_start[g];
    const int en = g_end[g];
    __syncthreads();

    for (int cs = s; cs < en; cs += CH) {
        const int nc = min(CH, en - cs);

        // ---- pass 1: e_i = emb_i . h (warp per node) ----
        const float4* h4 = reinterpret_cast<const float4*>(h_s);
        float4 hv0 = h4[lane];
        float4 hv1 = h4[lane + 32];
        for (int i = wid; i < nc; i += 8) {
            const float4* row = reinterpret_cast<const float4*>(emb + (size_t)(cs + i) * HIDDEN);
            float4 v0 = row[lane];
            float4 v1 = row[lane + 32];
            float d = v0.x * hv0.x + v0.y * hv0.y + v0.z * hv0.z + v0.w * hv0.w
                    + v1.x * hv1.x + v1.y * hv1.y + v1.z * hv1.z + v1.w * hv1.w;
            #pragma unroll
            for (int o = 16; o > 0; o >>= 1) d += __shfl_xor_sync(0xffffffffu, d, o);
            if (lane == 0) e_s[i] = d;
        }
        __syncthreads();

        // ---- chunk max -> new running max ----
        float lm = -CUDART_INF_F;
        for (int i = t; i < nc; i += 256) lm = fmaxf(lm, e_s[i]);
        #pragma unroll
        for (int o = 16; o > 0; o >>= 1) lm = fmaxf(lm, __shfl_xor_sync(0xffffffffu, lm, o));
        if (lane == 0) red[wid] = lm;
        __syncthreads();
        if (t < 32) {
            float v = (t < 8) ? red[t] : -CUDART_INF_F;
            #pragma unroll
            for (int o = 4; o > 0; o >>= 1) v = fmaxf(v, __shfl_xor_sync(0xffffffffu, v, o));
            if (t == 0) {
                float nm = fmaxf(sm_m, v);
                sm_scale = __expf(sm_m - nm);   // expf(-inf)=0 on first chunk
                sm_nm = nm;
                sm_m  = nm;
            }
        }
        __syncthreads();

        const float scale = sm_scale;
        const float nm    = sm_nm;
        R_s[t] *= scale;

        // ---- p_i = exp(e_i - m), S update ----
        float ls = 0.f;
        for (int i = t; i < nc; i += 256) {
            float p = expf(e_s[i] - nm);
            e_s[i] = p;
            ls += p;
        }
        #pragma unroll
        for (int o = 16; o > 0; o >>= 1) ls += __shfl_xor_sync(0xffffffffu, ls, o);
        if (lane == 0) red[wid] = ls;
        __syncthreads();
        if (t < 32) {
            float v = (t < 8) ? red[t] : 0.f;
            #pragma unroll
            for (int o = 4; o > 0; o >>= 1) v += __shfl_xor_sync(0xffffffffu, v, o);
            if (t == 0) sm_S = sm_S * scale + v;
        }
        __syncthreads();

        // ---- pass 2: R += p_i * emb_i  (reads hit L2) ----
        {
            const float* col = emb + (size_t)cs * HIDDEN + t;
            float a0 = 0.f, a1 = 0.f, a2 = 0.f, a3 = 0.f;
            int i = 0;
            for (; i + 4 <= nc; i += 4) {
                a0 += e_s[i + 0] * col[(size_t)(i + 0) * HIDDEN];
                a1 += e_s[i + 1] * col[(size_t)(i + 1) * HIDDEN];
                a2 += e_s[i + 2] * col[(size_t)(i + 2) * HIDDEN];
                a3 += e_s[i + 3] * col[(size_t)(i + 3) * HIDDEN];
            }
            for (; i < nc; i++) a0 += e_s[i] * col[(size_t)i * HIDDEN];
            R_s[t] += (a0 + a1) + (a2 + a3);
        }
        __syncthreads();
    }

    const float r = R_s[t] / (sm_S + 1e-16f);
    g_x[(size_t)g * XDIM + t]          = h_s[t];
    g_x[(size_t)g * XDIM + HIDDEN + t] = r;
}

// ---------------- GEMM: C[M,N] = act(A[M,K] @ B[N,K]^T + bias), bf16x3 split ----------------
__device__ __forceinline__ void mma_bf16(float c[4], const uint32_t a[4], const uint32_t b[2]) {
    asm volatile(
        "mma.sync.aligned.m16n8k16.row.col.f32.bf16.bf16.f32 "
        "{%0,%1,%2,%3}, {%4,%5,%6,%7}, {%8,%9}, {%0,%1,%2,%3};\n"
        : "+f"(c[0]), "+f"(c[1]), "+f"(c[2]), "+f"(c[3])
        : "r"(a[0]), "r"(a[1]), "r"(a[2]), "r"(a[3]), "r"(b[0]), "r"(b[1]));
}

#define BM 64
#define BN 128
#define BK 32
#define SPAD 2

__global__ void __launch_bounds__(256)
k_gemm(const float* __restrict__ A, const float* __restrict__ B,
       const float* __restrict__ bias, float* __restrict__ C,
       int M, int N, int K, int act) {
    __shared__ __nv_bfloat16 As_hi[BM][BK + SPAD];
    __shared__ __nv_bfloat16 As_lo[BM][BK + SPAD];
    __shared__ __nv_bfloat16 Bs_hi[BN][BK + SPAD];
    __shared__ __nv_bfloat16 Bs_lo[BN][BK + SPAD];

    const int tid   = threadIdx.x;
    const int lane  = tid & 31;
    const int wid   = tid >> 5;
    const int wm    = wid & 1;          // 2 warps in M
    const int wn    = wid >> 1;         // 4 warps in N
    const int g8    = lane >> 2;
    const int tg    = lane & 3;

    const int m0 = blockIdx.y * BM;
    const int n0 = blockIdx.x * BN;

    float acc[2][4][4];
    #pragma unroll
    for (int im = 0; im < 2; im++)
        #pragma unroll
        for (int in = 0; in < 4; in++)
            #pragma unroll
            for (int q = 0; q < 4; q++) acc[im][in][q] = 0.f;

    for (int kb = 0; kb < K; kb += BK) {
        // stage A (64x32) and B (128x32), converting fp32 -> bf16 hi/lo
        #pragma unroll
        for (int it = 0; it < 2; it++) {
            int f4 = tid + it * 256;                 // 512 float4s
            int row = f4 >> 3, c4 = (f4 & 7) * 4;
            float4 v = *reinterpret_cast<const float4*>(A + (size_t)(m0 + row) * K + kb + c4);
            float vv[4] = {v.x, v.y, v.z, v.w};
            #pragma unroll
            for (int u = 0; u < 4; u++) {
                __nv_bfloat16 hi = __float2bfloat16(vv[u]);
                As_hi[row][c4 + u] = hi;
                As_lo[row][c4 + u] = __float2bfloat16(vv[u] - __bfloat162float(hi));
            }
        }
        #pragma unroll
        for (int it = 0; it < 4; it++) {
            int f4 = tid + it * 256;                 // 1024 float4s
            int row = f4 >> 3, c4 = (f4 & 7) * 4;
            float4 v = *reinterpret_cast<const float4*>(B + (size_t)(n0 + row) * K + kb + c4);
            float vv[4] = {v.x, v.y, v.z, v.w};
            #pragma unroll
            for (int u = 0; u < 4; u++) {
                __nv_bfloat16 hi = __float2bfloat16(vv[u]);
                Bs_hi[row][c4 + u] = hi;
                Bs_lo[row][c4 + u] = __float2bfloat16(vv[u] - __bfloat162float(hi));
            }
        }
        __syncthreads();

        #pragma unroll
        for (int kk = 0; kk < BK; kk += 16) {
            uint32_t ah[2][4], al[2][4], bh[4][2], bl[4][2];
            #pragma unroll
            for (int im = 0; im < 2; im++) {
                int r = wm * 32 + im * 16 + g8;
                ah[im][0] = *reinterpret_cast<const uint32_t*>(&As_hi[r    ][kk + 2 * tg]);
                ah[im][1] = *reinterpret_cast<const uint32_t*>(&As_hi[r + 8][kk + 2 * tg]);
                ah[im][2] = *reinterpret_cast<const uint32_t*>(&As_hi[r    ][kk + 2 * tg + 8]);
                ah[im][3] = *reinterpret_cast<const uint32_t*>(&As_hi[r + 8][kk + 2 * tg + 8]);
                al[im][0] = *reinterpret_cast<const uint32_t*>(&As_lo[r    ][kk + 2 * tg]);
                al[im][1] = *reinterpret_cast<const uint32_t*>(&As_lo[r + 8][kk + 2 * tg]);
                al[im][2] = *reinterpret_cast<const uint32_t*>(&As_lo[r    ][kk + 2 * tg + 8]);
                al[im][3] = *reinterpret_cast<const uint32_t*>(&As_lo[r + 8][kk + 2 * tg + 8]);
            }
            #pragma unroll
            for (int in = 0; in < 4; in++) {
                int rn = wn * 32 + in * 8 + g8;
                bh[in][0] = *reinterpret_cast<const uint32_t*>(&Bs_hi[rn][kk + 2 * tg]);
                bh[in][1] = *reinterpret_cast<const uint32_t*>(&Bs_hi[rn][kk + 2 * tg + 8]);
                bl[in][0] = *reinterpret_cast<const uint32_t*>(&Bs_lo[rn][kk + 2 * tg]);
                bl[in][1] = *reinterpret_cast<const uint32_t*>(&Bs_lo[rn][kk + 2 * tg + 8]);
            }
            #pragma unroll
            for (int im = 0; im < 2; im++)
                #pragma unroll
                for (int in = 0; in < 4; in++) {
                    mma_bf16(acc[im][in], ah[im], bh[in]);   // hi*hi
                    mma_bf16(acc[im][in], ah[im], bl[in]);   // hi*lo
                    mma_bf16(acc[im][in], al[im], bh[in]);   // lo*hi
                }
        }
        __syncthreads();
    }

    // epilogue
    #pragma unroll
    for (int im = 0; im < 2; im++) {
        #pragma unroll
        for (int in = 0; in < 4; in++) {
            int row0 = m0 + wm * 32 + im * 16 + g8;
            int col  = n0 + wn * 32 + in * 8 + 2 * tg;
            float b0 = bias[col], b1 = bias[col + 1];
            float v0 = acc[im][in][0] + b0;
            float v1 = acc[im][in][1] + b1;
            float v2 = acc[im][in][2] + b0;
            float v3 = acc[im][in][3] + b1;
            if (act == 1) {
                v0 = fmaxf(v0, 0.f); v1 = fmaxf(v1, 0.f);
                v2 = fmaxf(v2, 0.f); v3 = fmaxf(v3, 0.f);
            }
            *reinterpret_cast<float2*>(&C[(size_t)row0 * N + col])       = make_float2(v0, v1);
            *reinterpret_cast<float2*>(&C[(size_t)(row0 + 8) * N + col]) = make_float2(v2, v3);
        }
    }
}

// ---------------- LSTM cell elementwise ----------------
__device__ __forceinline__ float sigf(float x) { return 1.f / (1.f + expf(-x)); }

__global__ void k_cell() {
    int g = blockIdx.x;
    int d = threadIdx.x;
    size_t gb = (size_t)g * GATESD;
    float gi = g_gates[gb + d];
    float gf = g_gates[gb + HIDDEN + d];
    float gg = g_gates[gb + 2 * HIDDEN + d];
    float go = g_gates[gb + 3 * HIDDEN + d];
    size_t hb = (size_t)g * HIDDEN + d;
    float c_old = g_c[hb];
    float c_new = sigf(gf) * c_old + sigf(gi) * tanhf(gg);
    float h_new = sigf(go) * tanhf(c_new);
    g_c[hb] = c_new;
    g_h[hb] = h_new;
    g_x[(size_t)g * XDIM + d] = h_new;   // refresh x[:, :256] for final readout
}

// ---------------- launch ----------------
extern "C" void kernel_launch(void* const* d_in, const int* in_sizes, int n_in,
                              void* d_out, int out_size) {
    const float* emb  = (const float*)d_in[0];
    const int*   bidx = (const int*)d_in[1];     // int32 (JAX x64 disabled)
    const float* W_ih = (const float*)d_in[2];
    const float* W_hh = (const float*)d_in[3];
    const float* b_ih = (const float*)d_in[4];
    const float* b_hh = (const float*)d_in[5];
    const float* W1   = (const float*)d_in[6];
    const float* b1   = (const float*)d_in[7];
    const float* W2   = (const float*)d_in[8];
    const float* b2   = (const float*)d_in[9];
    float* out = (float*)d_out;
    const int nn = in_sizes[1];

    float *p_x, *p_gates, *p_hdn, *p_Wc, *p_bc;
    cudaGetSymbolAddress((void**)&p_x,     g_x);
    cudaGetSymbolAddress((void**)&p_gates, g_gates);
    cudaGetSymbolAddress((void**)&p_hdn,   g_hdn);
    cudaGetSymbolAddress((void**)&p_Wc,    g_Wc);
    cudaGetSymbolAddress((void**)&p_bc,    g_bc);

    k_init<<<4096, 256>>>();
    k_prep<<<(GATESD * XDIM) / 256, 256>>>(W_ih, W_hh, b_ih, b_hh);
    k_segments<<<(nn + 255) / 256, 256>>>(bidx, nn);

    for (int s = 0; s < STEPS; s++) {
        k_attention<<<N_GRAPHS, 256>>>(emb);
        k_gemm<<<dim3(GATESD / BN, N_GRAPHS / BM), 256>>>(p_x, p_Wc, p_bc, p_gates,
                                                          N_GRAPHS, GATESD, XDIM, 0);
        k_cell<<<N_GRAPHS, 256>>>();
    }

    // MLP readout: hdn = relu([h|r] @ W1^T + b1); out = hdn @ W2^T + b2
    k_gemm<<<dim3(HIDDEN / BN, N_GRAPHS / BM), 256>>>(p_x, W1, b1, p_hdn,
                                                      N_GRAPHS, HIDDEN, XDIM, 1);
    k_gemm<<<dim3(HIDDEN / BN, N_GRAPHS / BM), 256>>>(p_hdn, W2, b2, out,
                                                      N_GRAPHS, HIDDEN, HIDDEN, 0);
}

// round 3
// speedup vs baseline: 1.3494x; 1.3494x over previous
#include <cuda_runtime.h>
#include <cuda_bf16.h>
#include <cstdint>
#include <math_constants.h>

#define N_GRAPHS 4096
#define HIDDEN   256
#define STEPS    6
#define GATESD   1024   // 4*HIDDEN
#define XDIM     512    // 2*HIDDEN

// ---------------- scratch (no allocation allowed) ----------------
__device__ float g_h[N_GRAPHS * HIDDEN];
__device__ float g_c[N_GRAPHS * HIDDEN];
__device__ float g_gates[N_GRAPHS * GATESD];
__device__ float g_bc[GATESD];                 // b_ih + b_hh
__device__ int   g_start[N_GRAPHS];
__device__ int   g_end[N_GRAPHS];
// bf16 hi/lo split operands
__device__ __nv_bfloat16 g_x_h[N_GRAPHS * XDIM],   g_x_l[N_GRAPHS * XDIM];
__device__ __nv_bfloat16 g_hdn_h[N_GRAPHS * HIDDEN], g_hdn_l[N_GRAPHS * HIDDEN];
__device__ __nv_bfloat16 g_Wc_h[GATESD * XDIM],    g_Wc_l[GATESD * XDIM];
__device__ __nv_bfloat16 g_W1_h[HIDDEN * XDIM],    g_W1_l[HIDDEN * XDIM];
__device__ __nv_bfloat16 g_W2_h[HIDDEN * HIDDEN],  g_W2_l[HIDDEN * HIDDEN];

__device__ __forceinline__ void split_bf16(float v, __nv_bfloat16& h, __nv_bfloat16& l) {
    h = __float2bfloat16(v);
    l = __float2bfloat16(v - __bfloat162float(h));
}

// ---------------- init ----------------
__global__ void k_init() {
    int i = blockIdx.x * blockDim.x + threadIdx.x;   // 1,048,576 threads
    g_h[i] = 0.f;
    g_c[i] = 0.f;
    if (i < N_GRAPHS) { g_start[i] = 0; g_end[i] = 0; }
}

// ---------------- fold + split weights ----------------
__global__ void k_prep(const float* __restrict__ W_ih, const float* __restrict__ W_hh,
                       const float* __restrict__ b_ih, const float* __restrict__ b_hh) {
    int i = blockIdx.x * blockDim.x + threadIdx.x;   // 1024*512
    int n = i >> 9;
    int k = i & 511;
    float v = W_ih[n * XDIM + k];
    if (k < HIDDEN) v += W_hh[n * HIDDEN + k];
    split_bf16(v, g_Wc_h[i], g_Wc_l[i]);
    if (i < GATESD) g_bc[i] = b_ih[i] + b_hh[i];
}

__global__ void k_conv(const float* __restrict__ src, __nv_bfloat16* __restrict__ dh,
                       __nv_bfloat16* __restrict__ dl, int n) {
    int i = blockIdx.x * blockDim.x + threadIdx.x;
    if (i < n) split_bf16(src[i], dh[i], dl[i]);
}

// ---------------- segment boundaries (batch_indices sorted, int32) ----------------
__global__ void k_segments(const int* __restrict__ idx, int nn) {
    int n = blockIdx.x * blockDim.x + threadIdx.x;
    if (n >= nn) return;
    int g = idx[n];
    if ((unsigned)g >= (unsigned)N_GRAPHS) return;
    if (n == 0      || idx[n - 1] != g) g_start[g] = n;
    if (n == nn - 1 || idx[n + 1] != g) g_end[g]   = n + 1;
}

// ---------------- single-pass attention: one CTA per graph ----------------
__global__ void __launch_bounds__(256, 4)
k_attention(const float* __restrict__ emb) {
    const int g    = blockIdx.x;
    const int t    = threadIdx.x;
    const int lane = t & 31;
    const int wid  = t >> 5;

    __shared__ float h_s[HIDDEN];
    __shared__ float Rall[8][HIDDEN];
    __shared__ float mw_s[8], Sw_s[8];

    h_s[t] = g_h[(size_t)g * HIDDEN + t];
    const int s  = g_start[g];
    const int en = g_end[g];
    __syncthreads();

    const float4* h4 = reinterpret_cast<const float4*>(h_s);
    const float4 hv0 = h4[lane];
    const float4 hv1 = h4[lane + 32];

    float m = -CUDART_INF_F, S = 0.f;
    float R[8] = {0.f, 0.f, 0.f, 0.f, 0.f, 0.f, 0.f, 0.f};

    // each warp owns nodes s+wid, s+wid+8, ... — one full row in registers,
    // online softmax accumulation, next row prefetched
    int i = s + wid;
    float4 c0, c1;
    bool have = (i < en);
    if (have) {
        const float4* r4 = reinterpret_cast<const float4*>(emb + (size_t)i * HIDDEN);
        c0 = r4[lane]; c1 = r4[lane + 32];
    }
    while (have) {
        const int nx = i + 8;
        const bool hn = nx < en;
        float4 n0f, n1f;
        if (hn) {
            const float4* r4 = reinterpret_cast<const float4*>(emb + (size_t)nx * HIDDEN);
            n0f = r4[lane]; n1f = r4[lane + 32];
        }
        float d = c0.x * hv0.x + c0.y * hv0.y + c0.z * hv0.z + c0.w * hv0.w
                + c1.x * hv1.x + c1.y * hv1.y + c1.z * hv1.z + c1.w * hv1.w;
        #pragma unroll
        for (int o = 16; o > 0; o >>= 1) d += __shfl_xor_sync(0xffffffffu, d, o);
        const float nm = fmaxf(m, d);
        const float sc = __expf(m - nm);   // first node: exp(-inf)=0
        const float p  = __expf(d - nm);
        S = S * sc + p;
        R[0] = R[0] * sc + p * c0.x;
        R[1] = R[1] * sc + p * c0.y;
        R[2] = R[2] * sc + p * c0.z;
        R[3] = R[3] * sc + p * c0.w;
        R[4] = R[4] * sc + p * c1.x;
        R[5] = R[5] * sc + p * c1.y;
        R[6] = R[6] * sc + p * c1.z;
        R[7] = R[7] * sc + p * c1.w;
        m = nm;
        i = nx; have = hn;
        if (hn) { c0 = n0f; c1 = n1f; }
    }

    if (lane == 0) { mw_s[wid] = m; Sw_s[wid] = S; }
    #pragma unroll
    for (int j = 0; j < 4; j++) {
        Rall[wid][lane * 4 + j]          = R[j];
        Rall[wid][128 + lane * 4 + j]    = R[4 + j];
    }
    __syncthreads();

    float r = 0.f;
    if (en > s) {
        float M = mw_s[0];
        #pragma unroll
        for (int w = 1; w < 8; w++) M = fmaxf(M, mw_s[w]);
        float Ss = 0.f, Rs = 0.f;
        #pragma unroll
        for (int w = 0; w < 8; w++) {
            const float f = __expf(mw_s[w] - M);
            Ss += f * Sw_s[w];
            Rs += f * Rall[w][t];
        }
        r = Rs / (Ss + 1e-16f);
    }

    const size_t xb = (size_t)g * XDIM;
    split_bf16(h_s[t], g_x_h[xb + t],          g_x_l[xb + t]);
    split_bf16(r,      g_x_h[xb + HIDDEN + t], g_x_l[xb + HIDDEN + t]);
}

// ---------------- GEMM: C = act(A @ B^T + bias), preconverted bf16 hi/lo, cp.async ----------------
__device__ __forceinline__ void mma_bf16(float c[4], const uint32_t a[4], const uint32_t b[2]) {
    asm volatile(
        "mma.sync.aligned.m16n8k16.row.col.f32.bf16.bf16.f32 "
        "{%0,%1,%2,%3}, {%4,%5,%6,%7}, {%8,%9}, {%0,%1,%2,%3};\n"
        : "+f"(c[0]), "+f"(c[1]), "+f"(c[2]), "+f"(c[3])
        : "r"(a[0]), "r"(a[1]), "r"(a[2]), "r"(a[3]), "r"(b[0]), "r"(b[1]));
}

__device__ __forceinline__ void cp16(__nv_bfloat16* dst, const __nv_bfloat16* src) {
    uint32_t d = (uint32_t)__cvta_generic_to_shared(dst);
    asm volatile("cp.async.cg.shared.global [%0], [%1], 16;\n" :: "r"(d), "l"(src));
}

#define BM 64
#define BN 128
#define BK 32
#define PITCH 40      // 32 + 8 halfs: conflict-free, 16B-aligned rows

// dynamic smem layout (halfs): A_h[2][64][40] A_l[...] B_h[2][128][40] B_l[...]
#define SZ_A (64 * PITCH)
#define SZ_B (128 * PITCH)
#define SMEM_HALFS (2 * SZ_A * 2 + 2 * SZ_B * 2)

__global__ void __launch_bounds__(256, 3)
k_gemm(const __nv_bfloat16* __restrict__ A_h, const __nv_bfloat16* __restrict__ A_l,
       const __nv_bfloat16* __restrict__ B_h, const __nv_bfloat16* __restrict__ B_l,
       const float* __restrict__ bias,
       float* __restrict__ C, __nv_bfloat16* __restrict__ C_h, __nv_bfloat16* __restrict__ C_l,
       int N, int K, int act) {
    extern __shared__ __nv_bfloat16 sm[];
    __nv_bfloat16* sA_h = sm;
    __nv_bfloat16* sA_l = sA_h + 2 * SZ_A;
    __nv_bfloat16* sB_h = sA_l + 2 * SZ_A;
    __nv_bfloat16* sB_l = sB_h + 2 * SZ_B;

    const int tid  = threadIdx.x;
    const int lane = tid & 31;
    const int wid  = tid >> 5;
    const int wm   = wid & 1;
    const int wn   = wid >> 1;
    const int g8   = lane >> 2;
    const int tg   = lane & 3;

    const int m0 = blockIdx.y * BM;
    const int n0 = blockIdx.x * BN;
    const int T  = K / BK;

    // staging coords
    const int ar = tid >> 2, aq = tid & 3;         // A: 64 rows x 4 quads
    const int br0 = tid >> 2, br1 = (tid + 256) >> 2; // B: 128 rows x 4 quads (2 chunks)

    float acc[2][4][4];
    #pragma unroll
    for (int im = 0; im < 2; im++)
        #pragma unroll
        for (int in = 0; in < 4; in++)
            #pragma unroll
            for (int q = 0; q < 4; q++) acc[im][in][q] = 0.f;

    auto stage = [&](int tile, int stg) {
        const int kb = tile * BK;
        __nv_bfloat16* dAh = sA_h + stg * SZ_A;
        __nv_bfloat16* dAl = sA_l + stg * SZ_A;
        __nv_bfloat16* dBh = sB_h + stg * SZ_B;
        __nv_bfloat16* dBl = sB_l + stg * SZ_B;
        cp16(dAh + ar * PITCH + aq * 8, A_h + (size_t)(m0 + ar) * K + kb + aq * 8);
        cp16(dAl + ar * PITCH + aq * 8, A_l + (size_t)(m0 + ar) * K + kb + aq * 8);
        cp16(dBh + br0 * PITCH + aq * 8, B_h + (size_t)(n0 + br0) * K + kb + aq * 8);
        cp16(dBh + br1 * PITCH + aq * 8, B_h + (size_t)(n0 + br1) * K + kb + aq * 8);
        cp16(dBl + br0 * PITCH + aq * 8, B_l + (size_t)(n0 + br0) * K + kb + aq * 8);
        cp16(dBl + br1 * PITCH + aq * 8, B_l + (size_t)(n0 + br1) * K + kb + aq * 8);
    };

    stage(0, 0);
    asm volatile("cp.async.commit_group;\n");

    for (int t = 0; t < T; t++) {
        const int stg = t & 1;
        if (t + 1 < T) stage(t + 1, (t + 1) & 1);
        asm volatile("cp.async.commit_group;\n");
        asm volatile("cp.async.wait_group 1;\n");
        __syncthreads();

        const __nv_bfloat16* Ah = sA_h + stg * SZ_A;
        const __nv_bfloat16* Al = sA_l + stg * SZ_A;
        const __nv_bfloat16* Bh = sB_h + stg * SZ_B;
        const __nv_bfloat16* Bl = sB_l + stg * SZ_B;

        #pragma unroll
        for (int kk = 0; kk < BK; kk += 16) {
            uint32_t ah[2][4], al[2][4], bh[4][2], bl[4][2];
            #pragma unroll
            for (int im = 0; im < 2; im++) {
                const int r = wm * 32 + im * 16 + g8;
                ah[im][0] = *reinterpret_cast<const uint32_t*>(Ah + r * PITCH + kk + 2 * tg);
                ah[im][1] = *reinterpret_cast<const uint32_t*>(Ah + (r + 8) * PITCH + kk + 2 * tg);
                ah[im][2] = *reinterpret_cast<const uint32_t*>(Ah + r * PITCH + kk + 2 * tg + 8);
                ah[im][3] = *reinterpret_cast<const uint32_t*>(Ah + (r + 8) * PITCH + kk + 2 * tg + 8);
                al[im][0] = *reinterpret_cast<const uint32_t*>(Al + r * PITCH + kk + 2 * tg);
                al[im][1] = *reinterpret_cast<const uint32_t*>(Al + (r + 8) * PITCH + kk + 2 * tg);
                al[im][2] = *reinterpret_cast<const uint32_t*>(Al + r * PITCH + kk + 2 * tg + 8);
                al[im][3] = *reinterpret_cast<const uint32_t*>(Al + (r + 8) * PITCH + kk + 2 * tg + 8);
            }
            #pragma unroll
            for (int in = 0; in < 4; in++) {
                const int rn = wn * 32 + in * 8 + g8;
                bh[in][0] = *reinterpret_cast<const uint32_t*>(Bh + rn * PITCH + kk + 2 * tg);
                bh[in][1] = *reinterpret_cast<const uint32_t*>(Bh + rn * PITCH + kk + 2 * tg + 8);
                bl[in][0] = *reinterpret_cast<const uint32_t*>(Bl + rn * PITCH + kk + 2 * tg);
                bl[in][1] = *reinterpret_cast<const uint32_t*>(Bl + rn * PITCH + kk + 2 * tg + 8);
            }
            #pragma unroll
            for (int im = 0; im < 2; im++)
                #pragma unroll
                for (int in = 0; in < 4; in++) {
                    mma_bf16(acc[im][in], ah[im], bh[in]);
                    mma_bf16(acc[im][in], ah[im], bl[in]);
                    mma_bf16(acc[im][in], al[im], bh[in]);
                }
        }
        __syncthreads();
    }

    #pragma unroll
    for (int im = 0; im < 2; im++) {
        #pragma unroll
        for (int in = 0; in < 4; in++) {
            const int row0 = m0 + wm * 32 + im * 16 + g8;
            const int col  = n0 + wn * 32 + in * 8 + 2 * tg;
            const float b0 = bias[col], b1 = bias[col + 1];
            float v0 = acc[im][in][0] + b0;
            float v1 = acc[im][in][1] + b1;
            float v2 = acc[im][in][2] + b0;
            float v3 = acc[im][in][3] + b1;
            if (act == 1) {
                v0 = fmaxf(v0, 0.f); v1 = fmaxf(v1, 0.f);
                v2 = fmaxf(v2, 0.f); v3 = fmaxf(v3, 0.f);
            }
            if (C) {
                *reinterpret_cast<float2*>(&C[(size_t)row0 * N + col])       = make_float2(v0, v1);
                *reinterpret_cast<float2*>(&C[(size_t)(row0 + 8) * N + col]) = make_float2(v2, v3);
            }
            if (C_h) {
                __nv_bfloat16 h0, l0, h1, l1;
                split_bf16(v0, h0, l0); split_bf16(v1, h1, l1);
                *reinterpret_cast<__nv_bfloat162*>(&C_h[(size_t)row0 * N + col]) = __nv_bfloat162(h0, h1);
                *reinterpret_cast<__nv_bfloat162*>(&C_l[(size_t)row0 * N + col]) = __nv_bfloat162(l0, l1);
                split_bf16(v2, h0, l0); split_bf16(v3, h1, l1);
                *reinterpret_cast<__nv_bfloat162*>(&C_h[(size_t)(row0 + 8) * N + col]) = __nv_bfloat162(h0, h1);
                *reinterpret_cast<__nv_bfloat162*>(&C_l[(size_t)(row0 + 8) * N + col]) = __nv_bfloat162(l0, l1);
            }
        }
    }
}

// ---------------- LSTM cell elementwise ----------------
__device__ __forceinline__ float sigf(float x) { return 1.f / (1.f + expf(-x)); }

__global__ void k_cell() {
    const int g = blockIdx.x;
    const int d = threadIdx.x;
    const size_t gb = (size_t)g * GATESD;
    const float gi = g_gates[gb + d];
    const float gf = g_gates[gb + HIDDEN + d];
    const float gg = g_gates[gb + 2 * HIDDEN + d];
    const float go = g_gates[gb + 3 * HIDDEN + d];
    const size_t hb = (size_t)g * HIDDEN + d;
    const float c_old = g_c[hb];
    const float c_new = sigf(gf) * c_old + sigf(gi) * tanhf(gg);
    const float h_new = sigf(go) * tanhf(c_new);
    g_c[hb] = c_new;
    g_h[hb] = h_new;
    split_bf16(h_new, g_x_h[(size_t)g * XDIM + d], g_x_l[(size_t)g * XDIM + d]);
}

// ---------------- launch ----------------
extern "C" void kernel_launch(void* const* d_in, const int* in_sizes, int n_in,
                              void* d_out, int out_size) {
    const float* emb  = (const float*)d_in[0];
    const int*   bidx = (const int*)d_in[1];     // int32 (JAX x64 disabled)
    const float* W_ih = (const float*)d_in[2];
    const float* W_hh = (const float*)d_in[3];
    const float* b_ih = (const float*)d_in[4];
    const float* b_hh = (const float*)d_in[5];
    const float* W1   = (const float*)d_in[6];
    const float* b1   = (const float*)d_in[7];
    const float* W2   = (const float*)d_in[8];
    const float* b2   = (const float*)d_in[9];
    float* out = (float*)d_out;
    const int nn = in_sizes[1];

    float *p_gates, *p_bc;
    __nv_bfloat16 *p_x_h, *p_x_l, *p_hdn_h, *p_hdn_l;
    __nv_bfloat16 *p_Wc_h, *p_Wc_l, *p_W1_h, *p_W1_l, *p_W2_h, *p_W2_l;
    cudaGetSymbolAddress((void**)&p_gates, g_gates);
    cudaGetSymbolAddress((void**)&p_bc,    g_bc);
    cudaGetSymbolAddress((void**)&p_x_h,   g_x_h);
    cudaGetSymbolAddress((void**)&p_x_l,   g_x_l);
    cudaGetSymbolAddress((void**)&p_hdn_h, g_hdn_h);
    cudaGetSymbolAddress((void**)&p_hdn_l, g_hdn_l);
    cudaGetSymbolAddress((void**)&p_Wc_h,  g_Wc_h);
    cudaGetSymbolAddress((void**)&p_Wc_l,  g_Wc_l);
    cudaGetSymbolAddress((void**)&p_W1_h,  g_W1_h);
    cudaGetSymbolAddress((void**)&p_W1_l,  g_W1_l);
    cudaGetSymbolAddress((void**)&p_W2_h,  g_W2_h);
    cudaGetSymbolAddress((void**)&p_W2_l,  g_W2_l);

    const int smem_bytes = SMEM_HALFS * (int)sizeof(__nv_bfloat16);   // 61440
    cudaFuncSetAttribute(k_gemm, cudaFuncAttributeMaxDynamicSharedMemorySize, smem_bytes);

    k_init<<<4096, 256>>>();
    k_prep<<<(GATESD * XDIM) / 256, 256>>>(W_ih, W_hh, b_ih, b_hh);
    k_conv<<<(HIDDEN * XDIM) / 256, 256>>>(W1, p_W1_h, p_W1_l, HIDDEN * XDIM);
    k_conv<<<(HIDDEN * HIDDEN) / 256, 256>>>(W2, p_W2_h, p_W2_l, HIDDEN * HIDDEN);
    k_segments<<<(nn + 255) / 256, 256>>>(bidx, nn);

    for (int s = 0; s < STEPS; s++) {
        k_attention<<<N_GRAPHS, 256>>>(emb);
        k_gemm<<<dim3(GATESD / BN, N_GRAPHS / BM), 256, smem_bytes>>>(
            p_x_h, p_x_l, p_Wc_h, p_Wc_l, p_bc, p_gates, nullptr, nullptr,
            GATESD, XDIM, 0);
        k_cell<<<N_GRAPHS, 256>>>();
    }

    // MLP readout
    k_gemm<<<dim3(HIDDEN / BN, N_GRAPHS / BM), 256, smem_bytes>>>(
        p_x_h, p_x_l, p_W1_h, p_W1_l, b1, nullptr, p_hdn_h, p_hdn_l,
        HIDDEN, XDIM, 1);
    k_gemm<<<dim3(HIDDEN / BN, N_GRAPHS / BM), 256, smem_bytes>>>(
        p_hdn_h, p_hdn_l, p_W2_h, p_W2_l, b2, out, nullptr, nullptr,
        HIDDEN, HIDDEN, 0);
}

// round 4
// speedup vs baseline: 1.3619x; 1.0093x over previous
#include <cuda_runtime.h>
#include <cuda_bf16.h>
#include <cstdint>
#include <math_constants.h>

#define N_GRAPHS 4096
#define HIDDEN   256
#define STEPS    6
#define GATESD   1024   // 4*HIDDEN
#define XDIM     512    // 2*HIDDEN

// ---------------- scratch (no allocation allowed) ----------------
__device__ float g_h[N_GRAPHS * HIDDEN];
__device__ float g_c[N_GRAPHS * HIDDEN];
__device__ float g_bc[GATESD];                 // b_ih + b_hh, gate-interleaved
__device__ int   g_start[N_GRAPHS];
__device__ int   g_end[N_GRAPHS];
// bf16 hi/lo split operands
__device__ __nv_bfloat16 g_x_h[N_GRAPHS * XDIM],     g_x_l[N_GRAPHS * XDIM];
__device__ __nv_bfloat16 g_hdn_h[N_GRAPHS * HIDDEN], g_hdn_l[N_GRAPHS * HIDDEN];
__device__ __nv_bfloat16 g_Wc_h[GATESD * XDIM],      g_Wc_l[GATESD * XDIM];   // gate-interleaved rows
__device__ __nv_bfloat16 g_W1_h[HIDDEN * XDIM],      g_W1_l[HIDDEN * XDIM];
__device__ __nv_bfloat16 g_W2_h[HIDDEN * HIDDEN],    g_W2_l[HIDDEN * HIDDEN];

__device__ __forceinline__ void split_bf16(float v, __nv_bfloat16& h, __nv_bfloat16& l) {
    h = __float2bfloat16(v);
    l = __float2bfloat16(v - __bfloat162float(h));
}

// ---------------- init ----------------
__global__ void k_init() {
    int i = blockIdx.x * blockDim.x + threadIdx.x;   // 1,048,576 threads
    g_h[i] = 0.f;
    g_c[i] = 0.f;
    if (i < N_GRAPHS) { g_start[i] = 0; g_end[i] = 0; }
}

// ---------------- fold + split weights (gate-interleaved: n' = 4d+gate) ----------------
__global__ void k_prep(const float* __restrict__ W_ih, const float* __restrict__ W_hh,
                       const float* __restrict__ b_ih, const float* __restrict__ b_hh) {
    int i = blockIdx.x * blockDim.x + threadIdx.x;   // 1024*512
    int np = i >> 9;                                  // interleaved row n'
    int k  = i & 511;
    int d = np >> 2, gate = np & 3;
    int orig = gate * HIDDEN + d;
    float v = W_ih[orig * XDIM + k];
    if (k < HIDDEN) v += W_hh[orig * HIDDEN + k];
    split_bf16(v, g_Wc_h[i], g_Wc_l[i]);
    if (i < GATESD) {
        int d2 = i >> 2, g2 = i & 3;
        int o2 = g2 * HIDDEN + d2;
        g_bc[i] = b_ih[o2] + b_hh[o2];
    }
}

__global__ void k_conv(const float* __restrict__ src, __nv_bfloat16* __restrict__ dh,
                       __nv_bfloat16* __restrict__ dl, int n) {
    int i = blockIdx.x * blockDim.x + threadIdx.x;
    if (i < n) split_bf16(src[i], dh[i], dl[i]);
}

// ---------------- segment boundaries (batch_indices sorted, int32) ----------------
__global__ void k_segments(const int* __restrict__ idx, int nn) {
    int n = blockIdx.x * blockDim.x + threadIdx.x;
    if (n >= nn) return;
    int g = idx[n];
    if ((unsigned)g >= (unsigned)N_GRAPHS) return;
    if (n == 0      || idx[n - 1] != g) g_start[g] = n;
    if (n == nn - 1 || idx[n + 1] != g) g_end[g]   = n + 1;
}

// ---------------- single-pass attention, depth-2 prefetch ----------------
__global__ void __launch_bounds__(256, 3)
k_attention(const float* __restrict__ emb) {
    const int g    = blockIdx.x;
    const int t    = threadIdx.x;
    const int lane = t & 31;
    const int wid  = t >> 5;

    __shared__ float h_s[HIDDEN];
    __shared__ float Rall[8][HIDDEN];
    __shared__ float mw_s[8], Sw_s[8];

    h_s[t] = g_h[(size_t)g * HIDDEN + t];
    const int s  = g_start[g];
    const int en = g_end[g];
    __syncthreads();

    const float4* h4 = reinterpret_cast<const float4*>(h_s);
    const float4 hv0 = h4[lane];
    const float4 hv1 = h4[lane + 32];

    float m = -CUDART_INF_F, S = 0.f;
    float R[8] = {0.f, 0.f, 0.f, 0.f, 0.f, 0.f, 0.f, 0.f};

    // warp owns nodes s+wid, s+wid+8, ...; 2 rows buffered, load 2 iterations ahead
    int ii = s + wid;
    float4 a0, a1, b0, b1;
    bool h0 = ii < en, h1 = (ii + 8) < en;
    if (h0) {
        const float4* r4 = reinterpret_cast<const float4*>(emb + (size_t)ii * HIDDEN);
        a0 = r4[lane]; a1 = r4[lane + 32];
    }
    if (h1) {
        const float4* r4 = reinterpret_cast<const float4*>(emb + (size_t)(ii + 8) * HIDDEN);
        b0 = r4[lane]; b1 = r4[lane + 32];
    }
    while (h0) {
        const bool h2 = (ii + 16) < en;
        float4 t0, t1;
        if (h2) {
            const float4* r4 = reinterpret_cast<const float4*>(emb + (size_t)(ii + 16) * HIDDEN);
            t0 = r4[lane]; t1 = r4[lane + 32];
        }
        float d = a0.x * hv0.x + a0.y * hv0.y + a0.z * hv0.z + a0.w * hv0.w
                + a1.x * hv1.x + a1.y * hv1.y + a1.z * hv1.z + a1.w * hv1.w;
        #pragma unroll
        for (int o = 16; o > 0; o >>= 1) d += __shfl_xor_sync(0xffffffffu, d, o);
        const float nm = fmaxf(m, d);
        const float sc = __expf(m - nm);   // first node: exp(-inf)=0
        const float p  = __expf(d - nm);
        S = S * sc + p;
        R[0] = R[0] * sc + p * a0.x;
        R[1] = R[1] * sc + p * a0.y;
        R[2] = R[2] * sc + p * a0.z;
        R[3] = R[3] * sc + p * a0.w;
        R[4] = R[4] * sc + p * a1.x;
        R[5] = R[5] * sc + p * a1.y;
        R[6] = R[6] * sc + p * a1.z;
        R[7] = R[7] * sc + p * a1.w;
        m = nm;
        a0 = b0; a1 = b1;
        b0 = t0; b1 = t1;
        h0 = h1; h1 = h2;
        ii += 8;
    }

    if (lane == 0) { mw_s[wid] = m; Sw_s[wid] = S; }
    #pragma unroll
    for (int j = 0; j < 4; j++) {
        Rall[wid][lane * 4 + j]       = R[j];
        Rall[wid][128 + lane * 4 + j] = R[4 + j];
    }
    __syncthreads();

    float r = 0.f;
    if (en > s) {
        float M = mw_s[0];
        #pragma unroll
        for (int w = 1; w < 8; w++) M = fmaxf(M, mw_s[w]);
        float Ss = 0.f, Rs = 0.f;
        #pragma unroll
        for (int w = 0; w < 8; w++) {
            const float f = __expf(mw_s[w] - M);
            Ss += f * Sw_s[w];
            Rs += f * Rall[w][t];
        }
        r = Rs / (Ss + 1e-16f);
    }

    const size_t xb = (size_t)g * XDIM;
    split_bf16(h_s[t], g_x_h[xb + t],          g_x_l[xb + t]);
    split_bf16(r,      g_x_h[xb + HIDDEN + t], g_x_l[xb + HIDDEN + t]);
}

// ---------------- GEMM: C = A @ B^T + bias, bf16x3, cp.async; 3 epilogue modes ----------------
// mode 0: write C as float
// mode 1: relu, write C_h/C_l bf16 split
// mode 2: fused LSTM cell (B rows gate-interleaved), updates g_c/g_h/g_x
__device__ __forceinline__ void mma_bf16(float c[4], const uint32_t a[4], const uint32_t b[2]) {
    asm volatile(
        "mma.sync.aligned.m16n8k16.row.col.f32.bf16.bf16.f32 "
        "{%0,%1,%2,%3}, {%4,%5,%6,%7}, {%8,%9}, {%0,%1,%2,%3};\n"
        : "+f"(c[0]), "+f"(c[1]), "+f"(c[2]), "+f"(c[3])
        : "r"(a[0]), "r"(a[1]), "r"(a[2]), "r"(a[3]), "r"(b[0]), "r"(b[1]));
}

__device__ __forceinline__ void cp16(__nv_bfloat16* dst, const __nv_bfloat16* src) {
    uint32_t d = (uint32_t)__cvta_generic_to_shared(dst);
    asm volatile("cp.async.cg.shared.global [%0], [%1], 16;\n" :: "r"(d), "l"(src));
}

__device__ __forceinline__ float sigf(float x) { return 1.f / (1.f + expf(-x)); }

#define BM 64
#define BN 128
#define BK 32
#define PITCH 40      // 32 + 8 halfs: conflict-free, 16B-aligned rows
#define CP 132        // epilogue float pitch

#define SZ_A (64 * PITCH)
#define SZ_B (128 * PITCH)
#define SMEM_HALFS (2 * SZ_A * 2 + 2 * SZ_B * 2)
#define SMEM_BYTES (SMEM_HALFS * 2)     // 61440; > 64*132*4 = 33792 epilogue floats

__global__ void __launch_bounds__(256, 3)
k_gemm(const __nv_bfloat16* __restrict__ A_h, const __nv_bfloat16* __restrict__ A_l,
       const __nv_bfloat16* __restrict__ B_h, const __nv_bfloat16* __restrict__ B_l,
       const float* __restrict__ bias,
       float* __restrict__ C, __nv_bfloat16* __restrict__ C_h, __nv_bfloat16* __restrict__ C_l,
       int N, int K, int mode) {
    extern __shared__ __nv_bfloat16 sm[];
    __nv_bfloat16* sA_h = sm;
    __nv_bfloat16* sA_l = sA_h + 2 * SZ_A;
    __nv_bfloat16* sB_h = sA_l + 2 * SZ_A;
    __nv_bfloat16* sB_l = sB_h + 2 * SZ_B;

    const int tid  = threadIdx.x;
    const int lane = tid & 31;
    const int wid  = tid >> 5;
    const int wm   = wid & 1;
    const int wn   = wid >> 1;
    const int g8   = lane >> 2;
    const int tg   = lane & 3;

    const int m0 = blockIdx.y * BM;
    const int n0 = blockIdx.x * BN;
    const int T  = K / BK;

    const int ar = tid >> 2, aq = tid & 3;
    const int br0 = tid >> 2, br1 = (tid + 256) >> 2;

    float acc[2][4][4];
    #pragma unroll
    for (int im = 0; im < 2; im++)
        #pragma unroll
        for (int in = 0; in < 4; in++)
            #pragma unroll
            for (int q = 0; q < 4; q++) acc[im][in][q] = 0.f;

    auto stage = [&](int tile, int stg) {
        const int kb = tile * BK;
        __nv_bfloat16* dAh = sA_h + stg * SZ_A;
        __nv_bfloat16* dAl = sA_l + stg * SZ_A;
        __nv_bfloat16* dBh = sB_h + stg * SZ_B;
        __nv_bfloat16* dBl = sB_l + stg * SZ_B;
        cp16(dAh + ar * PITCH + aq * 8, A_h + (size_t)(m0 + ar) * K + kb + aq * 8);
        cp16(dAl + ar * PITCH + aq * 8, A_l + (size_t)(m0 + ar) * K + kb + aq * 8);
        cp16(dBh + br0 * PITCH + aq * 8, B_h + (size_t)(n0 + br0) * K + kb + aq * 8);
        cp16(dBh + br1 * PITCH + aq * 8, B_h + (size_t)(n0 + br1) * K + kb + aq * 8);
        cp16(dBl + br0 * PITCH + aq * 8, B_l + (size_t)(n0 + br0) * K + kb + aq * 8);
        cp16(dBl + br1 * PITCH + aq * 8, B_l + (size_t)(n0 + br1) * K + kb + aq * 8);
    };

    stage(0, 0);
    asm volatile("cp.async.commit_group;\n");

    for (int t = 0; t < T; t++) {
        const int stg = t & 1;
        if (t + 1 < T) stage(t + 1, (t + 1) & 1);
        asm volatile("cp.async.commit_group;\n");
        asm volatile("cp.async.wait_group 1;\n");
        __syncthreads();

        const __nv_bfloat16* Ah = sA_h + stg * SZ_A;
        const __nv_bfloat16* Al = sA_l + stg * SZ_A;
        const __nv_bfloat16* Bh = sB_h + stg * SZ_B;
        const __nv_bfloat16* Bl = sB_l + stg * SZ_B;

        #pragma unroll
        for (int kk = 0; kk < BK; kk += 16) {
            uint32_t ah[2][4], al[2][4], bh[4][2], bl[4][2];
            #pragma unroll
            for (int im = 0; im < 2; im++) {
                const int r = wm * 32 + im * 16 + g8;
                ah[im][0] = *reinterpret_cast<const uint32_t*>(Ah + r * PITCH + kk + 2 * tg);
                ah[im][1] = *reinterpret_cast<const uint32_t*>(Ah + (r + 8) * PITCH + kk + 2 * tg);
                ah[im][2] = *reinterpret_cast<const uint32_t*>(Ah + r * PITCH + kk + 2 * tg + 8);
                ah[im][3] = *reinterpret_cast<const uint32_t*>(Ah + (r + 8) * PITCH + kk + 2 * tg + 8);
                al[im][0] = *reinterpret_cast<const uint32_t*>(Al + r * PITCH + kk + 2 * tg);
                al[im][1] = *reinterpret_cast<const uint32_t*>(Al + (r + 8) * PITCH + kk + 2 * tg);
                al[im][2] = *reinterpret_cast<const uint32_t*>(Al + r * PITCH + kk + 2 * tg + 8);
                al[im][3] = *reinterpret_cast<const uint32_t*>(Al + (r + 8) * PITCH + kk + 2 * tg + 8);
            }
            #pragma unroll
            for (int in = 0; in < 4; in++) {
                const int rn = wn * 32 + in * 8 + g8;
                bh[in][0] = *reinterpret_cast<const uint32_t*>(Bh + rn * PITCH + kk + 2 * tg);
                bh[in][1] = *reinterpret_cast<const uint32_t*>(Bh + rn * PITCH + kk + 2 * tg + 8);
                bl[in][0] = *reinterpret_cast<const uint32_t*>(Bl + rn * PITCH + kk + 2 * tg);
                bl[in][1] = *reinterpret_cast<const uint32_t*>(Bl + rn * PITCH + kk + 2 * tg + 8);
            }
            #pragma unroll
            for (int im = 0; im < 2; im++)
                #pragma unroll
                for (int in = 0; in < 4; in++) {
                    mma_bf16(acc[im][in], ah[im], bh[in]);
                    mma_bf16(acc[im][in], ah[im], bl[in]);
                    mma_bf16(acc[im][in], al[im], bh[in]);
                }
        }
        __syncthreads();
    }

    if (mode == 2) {
        // fused LSTM cell: dump acc+bias to smem, then compute cell per (graph, d)
        float* sC = reinterpret_cast<float*>(sm);
        #pragma unroll
        for (int im = 0; im < 2; im++)
            #pragma unroll
            for (int in = 0; in < 4; in++) {
                const int rl = wm * 32 + im * 16 + g8;
                const int cl = wn * 32 + in * 8 + 2 * tg;
                const float b0 = bias[n0 + cl], b1 = bias[n0 + cl + 1];
                sC[rl * CP + cl]           = acc[im][in][0] + b0;
                sC[rl * CP + cl + 1]       = acc[im][in][1] + b1;
                sC[(rl + 8) * CP + cl]     = acc[im][in][2] + b0;
                sC[(rl + 8) * CP + cl + 1] = acc[im][in][3] + b1;
            }
        __syncthreads();
        const int dbase = n0 >> 2;
        #pragma unroll
        for (int e = tid; e < 64 * 32; e += 256) {
            const int r  = e >> 5;
            const int dl = e & 31;
            const float4 gv = *reinterpret_cast<const float4*>(&sC[r * CP + dl * 4]); // i,f,g,o
            const int gi = m0 + r;
            const int d  = dbase + dl;
            const size_t hb = (size_t)gi * HIDDEN + d;
            const float c_old = g_c[hb];
            const float c_new = sigf(gv.y) * c_old + sigf(gv.x) * tanhf(gv.z);
            const float h_new = sigf(gv.w) * tanhf(c_new);
            g_c[hb] = c_new;
            g_h[hb] = h_new;
            split_bf16(h_new, g_x_h[(size_t)gi * XDIM + d], g_x_l[(size_t)gi * XDIM + d]);
        }
        return;
    }

    #pragma unroll
    for (int im = 0; im < 2; im++) {
        #pragma unroll
        for (int in = 0; in < 4; in++) {
            const int row0 = m0 + wm * 32 + im * 16 + g8;
            const int col  = n0 + wn * 32 + in * 8 + 2 * tg;
            const float b0 = bias[col], b1 = bias[col + 1];
            float v0 = acc[im][in][0] + b0;
            float v1 = acc[im][in][1] + b1;
            float v2 = acc[im][in][2] + b0;
            float v3 = acc[im][in][3] + b1;
            if (mode == 1) {
                v0 = fmaxf(v0, 0.f); v1 = fmaxf(v1, 0.f);
                v2 = fmaxf(v2, 0.f); v3 = fmaxf(v3, 0.f);
                __nv_bfloat16 h0, l0, h1, l1;
                split_bf16(v0, h0, l0); split_bf16(v1, h1, l1);
                *reinterpret_cast<__nv_bfloat162*>(&C_h[(size_t)row0 * N + col]) = __nv_bfloat162(h0, h1);
                *reinterpret_cast<__nv_bfloat162*>(&C_l[(size_t)row0 * N + col]) = __nv_bfloat162(l0, l1);
                split_bf16(v2, h0, l0); split_bf16(v3, h1, l1);
                *reinterpret_cast<__nv_bfloat162*>(&C_h[(size_t)(row0 + 8) * N + col]) = __nv_bfloat162(h0, h1);
                *reinterpret_cast<__nv_bfloat162*>(&C_l[(size_t)(row0 + 8) * N + col]) = __nv_bfloat162(l0, l1);
            } else {
                *reinterpret_cast<float2*>(&C[(size_t)row0 * N + col])       = make_float2(v0, v1);
                *reinterpret_cast<float2*>(&C[(size_t)(row0 + 8) * N + col]) = make_float2(v2, v3);
            }
        }
    }
}

// ---------------- launch ----------------
extern "C" void kernel_launch(void* const* d_in, const int* in_sizes, int n_in,
                              void* d_out, int out_size) {
    const float* emb  = (const float*)d_in[0];
    const int*   bidx = (const int*)d_in[1];     // int32 (JAX x64 disabled)
    const float* W_ih = (const float*)d_in[2];
    const float* W_hh = (const float*)d_in[3];
    const float* b_ih = (const float*)d_in[4];
    const float* b_hh = (const float*)d_in[5];
    const float* W1   = (const float*)d_in[6];
    const float* b1   = (const float*)d_in[7];
    const float* W2   = (const float*)d_in[8];
    const float* b2   = (const float*)d_in[9];
    float* out = (float*)d_out;
    const int nn = in_sizes[1];

    float *p_bc;
    __nv_bfloat16 *p_x_h, *p_x_l, *p_hdn_h, *p_hdn_l;
    __nv_bfloat16 *p_Wc_h, *p_Wc_l, *p_W1_h, *p_W1_l, *p_W2_h, *p_W2_l;
    cudaGetSymbolAddress((void**)&p_bc,    g_bc);
    cudaGetSymbolAddress((void**)&p_x_h,   g_x_h);
    cudaGetSymbolAddress((void**)&p_x_l,   g_x_l);
    cudaGetSymbolAddress((void**)&p_hdn_h, g_hdn_h);
    cudaGetSymbolAddress((void**)&p_hdn_l, g_hdn_l);
    cudaGetSymbolAddress((void**)&p_Wc_h,  g_Wc_h);
    cudaGetSymbolAddress((void**)&p_Wc_l,  g_Wc_l);
    cudaGetSymbolAddress((void**)&p_W1_h,  g_W1_h);
    cudaGetSymbolAddress((void**)&p_W1_l,  g_W1_l);
    cudaGetSymbolAddress((void**)&p_W2_h,  g_W2_h);
    cudaGetSymbolAddress((void**)&p_W2_l,  g_W2_l);

    cudaFuncSetAttribute(k_gemm, cudaFuncAttributeMaxDynamicSharedMemorySize, SMEM_BYTES);

    k_init<<<4096, 256>>>();
    k_prep<<<(GATESD * XDIM) / 256, 256>>>(W_ih, W_hh, b_ih, b_hh);
    k_conv<<<(HIDDEN * XDIM) / 256, 256>>>(W1, p_W1_h, p_W1_l, HIDDEN * XDIM);
    k_conv<<<(HIDDEN * HIDDEN) / 256, 256>>>(W2, p_W2_h, p_W2_l, HIDDEN * HIDDEN);
    k_segments<<<(nn + 255) / 256, 256>>>(bidx, nn);

    for (int s = 0; s < STEPS; s++) {
        k_attention<<<N_GRAPHS, 256>>>(emb);
        k_gemm<<<dim3(GATESD / BN, N_GRAPHS / BM), 256, SMEM_BYTES>>>(
            p_x_h, p_x_l, p_Wc_h, p_Wc_l, p_bc, nullptr, nullptr, nullptr,
            GATESD, XDIM, 2);
    }

    // MLP readout
    k_gemm<<<dim3(HIDDEN / BN, N_GRAPHS / BM), 256, SMEM_BYTES>>>(
        p_x_h, p_x_l, p_W1_h, p_W1_l, b1, nullptr, p_hdn_h, p_hdn_l,
        HIDDEN, XDIM, 1);
    k_gemm<<<dim3(HIDDEN / BN, N_GRAPHS / BM), 256, SMEM_BYTES>>>(
        p_hdn_h, p_hdn_l, p_W2_h, p_W2_l, b2, out, nullptr, nullptr,
        HIDDEN, HIDDEN, 0);
}

// round 6
// speedup vs baseline: 1.4093x; 1.0348x over previous
#include <cuda_runtime.h>
#include <cuda_bf16.h>
#include <cstdint>
#include <math_constants.h>

#define N_GRAPHS 4096
#define HIDDEN   256
#define STEPS    6
#define GATESD   1024   // 4*HIDDEN
#define XDIM     512    // 2*HIDDEN

// ---------------- scratch (no allocation allowed) ----------------
__device__ float g_h[N_GRAPHS * HIDDEN];
__device__ float g_c[N_GRAPHS * HIDDEN];
__device__ float g_bc[GATESD];                 // b_ih + b_hh, gate-interleaved
__device__ int   g_start[N_GRAPHS];
__device__ int   g_end[N_GRAPHS];
__device__ __nv_bfloat16 g_x_h[N_GRAPHS * XDIM],     g_x_l[N_GRAPHS * XDIM];
__device__ __nv_bfloat16 g_hdn_h[N_GRAPHS * HIDDEN], g_hdn_l[N_GRAPHS * HIDDEN];
__device__ __nv_bfloat16 g_Wc_h[GATESD * XDIM],      g_Wc_l[GATESD * XDIM];   // gate-interleaved rows
__device__ __nv_bfloat16 g_W1_h[HIDDEN * XDIM],      g_W1_l[HIDDEN * XDIM];
__device__ __nv_bfloat16 g_W2_h[HIDDEN * HIDDEN],    g_W2_l[HIDDEN * HIDDEN];

__device__ __forceinline__ void split_bf16(float v, __nv_bfloat16& h, __nv_bfloat16& l) {
    h = __float2bfloat16(v);
    l = __float2bfloat16(v - __bfloat162float(h));
}
__device__ __forceinline__ float sigf(float x) { return 1.f / (1.f + expf(-x)); }

// ---------------- init ----------------
__global__ void k_init() {
    int i = blockIdx.x * blockDim.x + threadIdx.x;
    g_h[i] = 0.f;
    g_c[i] = 0.f;
    if (i < N_GRAPHS) { g_start[i] = 0; g_end[i] = 0; }
}

// ---------------- fold + split weights (gate-interleaved: n' = 4d+gate) ----------------
__global__ void k_prep(const float* __restrict__ W_ih, const float* __restrict__ W_hh,
                       const float* __restrict__ b_ih, const float* __restrict__ b_hh) {
    int i = blockIdx.x * blockDim.x + threadIdx.x;
    int np = i >> 9;
    int k  = i & 511;
    int d = np >> 2, gate = np & 3;
    int orig = gate * HIDDEN + d;
    float v = W_ih[orig * XDIM + k];
    if (k < HIDDEN) v += W_hh[orig * HIDDEN + k];
    split_bf16(v, g_Wc_h[i], g_Wc_l[i]);
    if (i < GATESD) {
        int d2 = i >> 2, g2 = i & 3;
        int o2 = g2 * HIDDEN + d2;
        g_bc[i] = b_ih[o2] + b_hh[o2];
    }
}

__global__ void k_conv(const float* __restrict__ src, __nv_bfloat16* __restrict__ dh,
                       __nv_bfloat16* __restrict__ dl, int n) {
    int i = blockIdx.x * blockDim.x + threadIdx.x;
    if (i < n) split_bf16(src[i], dh[i], dl[i]);
}

// ---------------- segment boundaries ----------------
__global__ void k_segments(const int* __restrict__ idx, int nn) {
    int n = blockIdx.x * blockDim.x + threadIdx.x;
    if (n >= nn) return;
    int g = idx[n];
    if ((unsigned)g >= (unsigned)N_GRAPHS) return;
    if (n == 0      || idx[n - 1] != g) g_start[g] = n;
    if (n == nn - 1 || idx[n + 1] != g) g_end[g]   = n + 1;
}

// ---------------- single-pass attention ----------------
__global__ void __launch_bounds__(256, 3)
k_attention(const float* __restrict__ emb) {
    const int g    = blockIdx.x;
    const int t    = threadIdx.x;
    const int lane = t & 31;
    const int wid  = t >> 5;

    __shared__ float h_s[HIDDEN];
    __shared__ float Rall[8][HIDDEN];
    __shared__ float mw_s[8], Sw_s[8];

    h_s[t] = g_h[(size_t)g * HIDDEN + t];
    const int s  = g_start[g];
    const int en = g_end[g];
    __syncthreads();

    const float4* h4 = reinterpret_cast<const float4*>(h_s);
    const float4 hv0 = h4[lane];
    const float4 hv1 = h4[lane + 32];

    float m = -CUDART_INF_F, S = 0.f;
    float R[8] = {0.f, 0.f, 0.f, 0.f, 0.f, 0.f, 0.f, 0.f};

    int ii = s + wid;
    float4 a0, a1, b0, b1;
    bool h0 = ii < en, h1 = (ii + 8) < en;
    if (h0) {
        const float4* r4 = reinterpret_cast<const float4*>(emb + (size_t)ii * HIDDEN);
        a0 = r4[lane]; a1 = r4[lane + 32];
    }
    if (h1) {
        const float4* r4 = reinterpret_cast<const float4*>(emb + (size_t)(ii + 8) * HIDDEN);
        b0 = r4[lane]; b1 = r4[lane + 32];
    }
    while (h0) {
        const bool h2 = (ii + 16) < en;
        float4 t0, t1;
        if (h2) {
            const float4* r4 = reinterpret_cast<const float4*>(emb + (size_t)(ii + 16) * HIDDEN);
            t0 = r4[lane]; t1 = r4[lane + 32];
        }
        float d = a0.x * hv0.x + a0.y * hv0.y + a0.z * hv0.z + a0.w * hv0.w
                + a1.x * hv1.x + a1.y * hv1.y + a1.z * hv1.z + a1.w * hv1.w;
        #pragma unroll
        for (int o = 16; o > 0; o >>= 1) d += __shfl_xor_sync(0xffffffffu, d, o);
        const float nm = fmaxf(m, d);
        const float sc = __expf(m - nm);
        const float p  = __expf(d - nm);
        S = S * sc + p;
        R[0] = R[0] * sc + p * a0.x;
        R[1] = R[1] * sc + p * a0.y;
        R[2] = R[2] * sc + p * a0.z;
        R[3] = R[3] * sc + p * a0.w;
        R[4] = R[4] * sc + p * a1.x;
        R[5] = R[5] * sc + p * a1.y;
        R[6] = R[6] * sc + p * a1.z;
        R[7] = R[7] * sc + p * a1.w;
        m = nm;
        a0 = b0; a1 = b1;
        b0 = t0; b1 = t1;
        h0 = h1; h1 = h2;
        ii += 8;
    }

    if (lane == 0) { mw_s[wid] = m; Sw_s[wid] = S; }
    #pragma unroll
    for (int j = 0; j < 4; j++) {
        Rall[wid][lane * 4 + j]       = R[j];
        Rall[wid][128 + lane * 4 + j] = R[4 + j];
    }
    __syncthreads();

    float r = 0.f;
    if (en > s) {
        float M = mw_s[0];
        #pragma unroll
        for (int w = 1; w < 8; w++) M = fmaxf(M, mw_s[w]);
        float Ss = 0.f, Rs = 0.f;
        #pragma unroll
        for (int w = 0; w < 8; w++) {
            const float f = __expf(mw_s[w] - M);
            Ss += f * Sw_s[w];
            Rs += f * Rall[w][t];
        }
        r = Rs / (Ss + 1e-16f);
    }

    const size_t xb = (size_t)g * XDIM;
    split_bf16(h_s[t], g_x_h[xb + t],          g_x_l[xb + t]);
    split_bf16(r,      g_x_h[xb + HIDDEN + t], g_x_l[xb + HIDDEN + t]);
}

// ---------------- shared MMA helpers ----------------
__device__ __forceinline__ void mma_bf16(float c[4], const uint32_t a[4], const uint32_t b[2]) {
    asm volatile(
        "mma.sync.aligned.m16n8k16.row.col.f32.bf16.bf16.f32 "
        "{%0,%1,%2,%3}, {%4,%5,%6,%7}, {%8,%9}, {%0,%1,%2,%3};\n"
        : "+f"(c[0]), "+f"(c[1]), "+f"(c[2]), "+f"(c[3])
        : "r"(a[0]), "r"(a[1]), "r"(a[2]), "r"(a[3]), "r"(b[0]), "r"(b[1]));
}
__device__ __forceinline__ void cp16(__nv_bfloat16* dst, const __nv_bfloat16* src) {
    uint32_t d = (uint32_t)__cvta_generic_to_shared(dst);
    asm volatile("cp.async.cg.shared.global [%0], [%1], 16;\n" :: "r"(d), "l"(src));
}

// ======== gates GEMM, single wave: 128x128 tiles, fused LSTM cell ========
// grid (8, 32) = 256 CTAs, 2 CTAs/SM. warps 4(M)x2(N), warp tile 32x64.
#define GP 40                      // smem pitch (halfs)
#define GSZ (128 * GP)             // one operand array (halfs)
#define G_SMEM_BYTES (2 * 4 * GSZ * 2)   // 2 buffers x {Ah,Al,Bh,Bl} x bytes = 81920
#define GCP 132                    // epilogue float pitch

__global__ void __launch_bounds__(256, 2)
k_gates(const __nv_bfloat16* __restrict__ A_h, const __nv_bfloat16* __restrict__ A_l,
        const __nv_bfloat16* __restrict__ B_h, const __nv_bfloat16* __restrict__ B_l,
        const float* __restrict__ bias) {
    extern __shared__ __nv_bfloat16 sg[];
    // buffer layout: [stg][Ah|Al|Bh|Bl]
    __shared__ float sbias[128];

    const int tid  = threadIdx.x;
    const int lane = tid & 31;
    const int wid  = tid >> 5;
    const int wm   = wid & 3;          // 4 warps in M
    const int wn   = wid >> 2;         // 2 warps in N
    const int g8   = lane >> 2;
    const int tg   = lane & 3;

    const int m0 = blockIdx.y * 128;
    const int n0 = blockIdx.x * 128;
    const int dbase = n0 >> 2;

    if (tid < 128) sbias[tid] = bias[n0 + tid];

    float acc[2][8][4];
    #pragma unroll
    for (int im = 0; im < 2; im++)
        #pragma unroll
        for (int in = 0; in < 8; in++)
            #pragma unroll
            for (int q = 0; q < 4; q++) acc[im][in][q] = 0.f;

    // staging: per array 512 x 16B units (128 rows x 4 quads); 256 threads -> 2 each
    const int r0 = tid >> 2, q0 = tid & 3;
    const int r1 = (tid + 256) >> 2, q1 = tid & 3;

    auto stage = [&](int t) {
        const int stg = t & 1;
        const int kb = t * 32;
        __nv_bfloat16* base = sg + stg * 4 * GSZ;
        __nv_bfloat16* dAh = base;
        __nv_bfloat16* dAl = base + GSZ;
        __nv_bfloat16* dBh = base + 2 * GSZ;
        __nv_bfloat16* dBl = base + 3 * GSZ;
        cp16(dAh + r0 * GP + q0 * 8, A_h + (size_t)(m0 + r0) * XDIM + kb + q0 * 8);
        cp16(dAh + r1 * GP + q1 * 8, A_h + (size_t)(m0 + r1) * XDIM + kb + q1 * 8);
        cp16(dAl + r0 * GP + q0 * 8, A_l + (size_t)(m0 + r0) * XDIM + kb + q0 * 8);
        cp16(dAl + r1 * GP + q1 * 8, A_l + (size_t)(m0 + r1) * XDIM + kb + q1 * 8);
        cp16(dBh + r0 * GP + q0 * 8, B_h + (size_t)(n0 + r0) * XDIM + kb + q0 * 8);
        cp16(dBh + r1 * GP + q1 * 8, B_h + (size_t)(n0 + r1) * XDIM + kb + q1 * 8);
        cp16(dBl + r0 * GP + q0 * 8, B_l + (size_t)(n0 + r0) * XDIM + kb + q0 * 8);
        cp16(dBl + r1 * GP + q1 * 8, B_l + (size_t)(n0 + r1) * XDIM + kb + q1 * 8);
    };

    stage(0);
    asm volatile("cp.async.commit_group;\n");

    const int T = XDIM / 32;   // 16
    for (int t = 0; t < T; t++) {
        const int stg = t & 1;
        if (t + 1 < T) stage(t + 1);
        asm volatile("cp.async.commit_group;\n");
        asm volatile("cp.async.wait_group 1;\n");
        __syncthreads();

        const __nv_bfloat16* base = sg + stg * 4 * GSZ;
        const __nv_bfloat16* Ah = base;
        const __nv_bfloat16* Al = base + GSZ;
        const __nv_bfloat16* Bh = base + 2 * GSZ;
        const __nv_bfloat16* Bl = base + 3 * GSZ;

        #pragma unroll
        for (int kk = 0; kk < 32; kk += 16) {
            uint32_t ah[2][4], al[2][4];
            #pragma unroll
            for (int im = 0; im < 2; im++) {
                const int r = wm * 32 + im * 16 + g8;
                ah[im][0] = *reinterpret_cast<const uint32_t*>(Ah + r * GP + kk + 2 * tg);
                ah[im][1] = *reinterpret_cast<const uint32_t*>(Ah + (r + 8) * GP + kk + 2 * tg);
                ah[im][2] = *reinterpret_cast<const uint32_t*>(Ah + r * GP + kk + 2 * tg + 8);
                ah[im][3] = *reinterpret_cast<const uint32_t*>(Ah + (r + 8) * GP + kk + 2 * tg + 8);
                al[im][0] = *reinterpret_cast<const uint32_t*>(Al + r * GP + kk + 2 * tg);
                al[im][1] = *reinterpret_cast<const uint32_t*>(Al + (r + 8) * GP + kk + 2 * tg);
                al[im][2] = *reinterpret_cast<const uint32_t*>(Al + r * GP + kk + 2 * tg + 8);
                al[im][3] = *reinterpret_cast<const uint32_t*>(Al + (r + 8) * GP + kk + 2 * tg + 8);
            }
            #pragma unroll
            for (int in = 0; in < 8; in++) {
                const int rn = wn * 64 + in * 8 + g8;
                uint32_t bh[2], bl[2];
                bh[0] = *reinterpret_cast<const uint32_t*>(Bh + rn * GP + kk + 2 * tg);
                bh[1] = *reinterpret_cast<const uint32_t*>(Bh + rn * GP + kk + 2 * tg + 8);
                bl[0] = *reinterpret_cast<const uint32_t*>(Bl + rn * GP + kk + 2 * tg);
                bl[1] = *reinterpret_cast<const uint32_t*>(Bl + rn * GP + kk + 2 * tg + 8);
                #pragma unroll
                for (int im = 0; im < 2; im++) {
                    mma_bf16(acc[im][in], ah[im], bh);
                    mma_bf16(acc[im][in], ah[im], bl);
                    mma_bf16(acc[im][in], al[im], bh);
                }
            }
        }
        __syncthreads();
    }

    // ---- fused LSTM cell epilogue ----
    float* sC = reinterpret_cast<float*>(sg);   // 128 x GCP floats (67584 B < 81920)
    #pragma unroll
    for (int im = 0; im < 2; im++)
        #pragma unroll
        for (int in = 0; in < 8; in++) {
            const int rl = wm * 32 + im * 16 + g8;
            const int cl = wn * 64 + in * 8 + 2 * tg;
            sC[rl * GCP + cl]           = acc[im][in][0] + sbias[cl];
            sC[rl * GCP + cl + 1]       = acc[im][in][1] + sbias[cl + 1];
            sC[(rl + 8) * GCP + cl]     = acc[im][in][2] + sbias[cl];
            sC[(rl + 8) * GCP + cl + 1] = acc[im][in][3] + sbias[cl + 1];
        }
    __syncthreads();

    #pragma unroll
    for (int it = 0; it < 16; it++) {
        const int idx = tid + it * 256;      // 4096 = 128 rows x 32 d
        const int row = idx >> 5, dl = idx & 31;
        const float4 gv = *reinterpret_cast<const float4*>(&sC[row * GCP + dl * 4]); // i,f,g,o
        const int gi = m0 + row;
        const int d  = dbase + dl;
        const size_t hb = (size_t)gi * HIDDEN + d;
        const float c_old = g_c[hb];
        const float c_new = sigf(gv.y) * c_old + sigf(gv.x) * tanhf(gv.z);
        const float h_new = sigf(gv.w) * tanhf(c_new);
        g_c[hb] = c_new;
        g_h[hb] = h_new;
        split_bf16(h_new, g_x_h[(size_t)gi * XDIM + d], g_x_l[(size_t)gi * XDIM + d]);
    }
}

// ---------------- generic GEMM for the two MLP launches ----------------
#define BM 64
#define BN 128
#define BK 32
#define PITCH 40
#define SZ_A (64 * PITCH)
#define SZ_B (128 * PITCH)
#define SMEM_HALFS (2 * SZ_A * 2 + 2 * SZ_B * 2)
#define SMEM_BYTES (SMEM_HALFS * 2)

__global__ void __launch_bounds__(256, 3)
k_gemm(const __nv_bfloat16* __restrict__ A_h, const __nv_bfloat16* __restrict__ A_l,
       const __nv_bfloat16* __restrict__ B_h, const __nv_bfloat16* __restrict__ B_l,
       const float* __restrict__ bias,
       float* __restrict__ C, __nv_bfloat16* __restrict__ C_h, __nv_bfloat16* __restrict__ C_l,
       int N, int K, int mode) {
    extern __shared__ __nv_bfloat16 sm[];
    __nv_bfloat16* sA_h = sm;
    __nv_bfloat16* sA_l = sA_h + 2 * SZ_A;
    __nv_bfloat16* sB_h = sA_l + 2 * SZ_A;
    __nv_bfloat16* sB_l = sB_h + 2 * SZ_B;

    const int tid  = threadIdx.x;
    const int lane = tid & 31;
    const int wid  = tid >> 5;
    const int wm   = wid & 1;
    const int wn   = wid >> 1;
    const int g8   = lane >> 2;
    const int tg   = lane & 3;

    const int m0 = blockIdx.y * BM;
    const int n0 = blockIdx.x * BN;
    const int T  = K / BK;

    const int ar = tid >> 2, aq = tid & 3;
    const int br0 = tid >> 2, br1 = (tid + 256) >> 2;

    float acc[2][4][4];
    #pragma unroll
    for (int im = 0; im < 2; im++)
        #pragma unroll
        for (int in = 0; in < 4; in++)
            #pragma unroll
            for (int q = 0; q < 4; q++) acc[im][in][q] = 0.f;

    auto stage = [&](int tile, int stg) {
        const int kb = tile * BK;
        __nv_bfloat16* dAh = sA_h + stg * SZ_A;
        __nv_bfloat16* dAl = sA_l + stg * SZ_A;
        __nv_bfloat16* dBh = sB_h + stg * SZ_B;
        __nv_bfloat16* dBl = sB_l + stg * SZ_B;
        cp16(dAh + ar * PITCH + aq * 8, A_h + (size_t)(m0 + ar) * K + kb + aq * 8);
        cp16(dAl + ar * PITCH + aq * 8, A_l + (size_t)(m0 + ar) * K + kb + aq * 8);
        cp16(dBh + br0 * PITCH + aq * 8, B_h + (size_t)(n0 + br0) * K + kb + aq * 8);
        cp16(dBh + br1 * PITCH + aq * 8, B_h + (size_t)(n0 + br1) * K + kb + aq * 8);
        cp16(dBl + br0 * PITCH + aq * 8, B_l + (size_t)(n0 + br0) * K + kb + aq * 8);
        cp16(dBl + br1 * PITCH + aq * 8, B_l + (size_t)(n0 + br1) * K + kb + aq * 8);
    };

    stage(0, 0);
    asm volatile("cp.async.commit_group;\n");

    for (int t = 0; t < T; t++) {
        const int stg = t & 1;
        if (t + 1 < T) stage(t + 1, (t + 1) & 1);
        asm volatile("cp.async.commit_group;\n");
        asm volatile("cp.async.wait_group 1;\n");
        __syncthreads();

        const __nv_bfloat16* Ah = sA_h + stg * SZ_A;
        const __nv_bfloat16* Al = sA_l + stg * SZ_A;
        const __nv_bfloat16* Bh = sB_h + stg * SZ_B;
        const __nv_bfloat16* Bl = sB_l + stg * SZ_B;

        #pragma unroll
        for (int kk = 0; kk < BK; kk += 16) {
            uint32_t ah[2][4], al[2][4], bh[4][2], bl[4][2];
            #pragma unroll
            for (int im = 0; im < 2; im++) {
                const int r = wm * 32 + im * 16 + g8;
                ah[im][0] = *reinterpret_cast<const uint32_t*>(Ah + r * PITCH + kk + 2 * tg);
                ah[im][1] = *reinterpret_cast<const uint32_t*>(Ah + (r + 8) * PITCH + kk + 2 * tg);
                ah[im][2] = *reinterpret_cast<const uint32_t*>(Ah + r * PITCH + kk + 2 * tg + 8);
                ah[im][3] = *reinterpret_cast<const uint32_t*>(Ah + (r + 8) * PITCH + kk + 2 * tg + 8);
                al[im][0] = *reinterpret_cast<const uint32_t*>(Al + r * PITCH + kk + 2 * tg);
                al[im][1] = *reinterpret_cast<const uint32_t*>(Al + (r + 8) * PITCH + kk + 2 * tg);
                al[im][2] = *reinterpret_cast<const uint32_t*>(Al + r * PITCH + kk + 2 * tg + 8);
                al[im][3] = *reinterpret_cast<const uint32_t*>(Al + (r + 8) * PITCH + kk + 2 * tg + 8);
            }
            #pragma unroll
            for (int in = 0; in < 4; in++) {
                const int rn = wn * 32 + in * 8 + g8;
                bh[in][0] = *reinterpret_cast<const uint32_t*>(Bh + rn * PITCH + kk + 2 * tg);
                bh[in][1] = *reinterpret_cast<const uint32_t*>(Bh + rn * PITCH + kk + 2 * tg + 8);
                bl[in][0] = *reinterpret_cast<const uint32_t*>(Bl + rn * PITCH + kk + 2 * tg);
                bl[in][1] = *reinterpret_cast<const uint32_t*>(Bl + rn * PITCH + kk + 2 * tg + 8);
            }
            #pragma unroll
            for (int im = 0; im < 2; im++)
                #pragma unroll
                for (int in = 0; in < 4; in++) {
                    mma_bf16(acc[im][in], ah[im], bh[in]);
                    mma_bf16(acc[im][in], ah[im], bl[in]);
                    mma_bf16(acc[im][in], al[im], bh[in]);
                }
        }
        __syncthreads();
    }

    #pragma unroll
    for (int im = 0; im < 2; im++) {
        #pragma unroll
        for (int in = 0; in < 4; in++) {
            const int row0 = m0 + wm * 32 + im * 16 + g8;
            const int col  = n0 + wn * 32 + in * 8 + 2 * tg;
            const float b0 = bias[col], b1 = bias[col + 1];
            float v0 = acc[im][in][0] + b0;
            float v1 = acc[im][in][1] + b1;
            float v2 = acc[im][in][2] + b0;
            float v3 = acc[im][in][3] + b1;
            if (mode == 1) {
                v0 = fmaxf(v0, 0.f); v1 = fmaxf(v1, 0.f);
                v2 = fmaxf(v2, 0.f); v3 = fmaxf(v3, 0.f);
                __nv_bfloat16 h0, l0, h1, l1;
                split_bf16(v0, h0, l0); split_bf16(v1, h1, l1);
                *reinterpret_cast<__nv_bfloat162*>(&C_h[(size_t)row0 * N + col]) = __nv_bfloat162(h0, h1);
                *reinterpret_cast<__nv_bfloat162*>(&C_l[(size_t)row0 * N + col]) = __nv_bfloat162(l0, l1);
                split_bf16(v2, h0, l0); split_bf16(v3, h1, l1);
                *reinterpret_cast<__nv_bfloat162*>(&C_h[(size_t)(row0 + 8) * N + col]) = __nv_bfloat162(h0, h1);
                *reinterpret_cast<__nv_bfloat162*>(&C_l[(size_t)(row0 + 8) * N + col]) = __nv_bfloat162(l0, l1);
            } else {
                *reinterpret_cast<float2*>(&C[(size_t)row0 * N + col])       = make_float2(v0, v1);
                *reinterpret_cast<float2*>(&C[(size_t)(row0 + 8) * N + col]) = make_float2(v2, v3);
            }
        }
    }
}

// ---------------- launch ----------------
extern "C" void kernel_launch(void* const* d_in, const int* in_sizes, int n_in,
                              void* d_out, int out_size) {
    const float* emb  = (const float*)d_in[0];
    const int*   bidx = (const int*)d_in[1];
    const float* W_ih = (const float*)d_in[2];
    const float* W_hh = (const float*)d_in[3];
    const float* b_ih = (const float*)d_in[4];
    const float* b_hh = (const float*)d_in[5];
    const float* W1   = (const float*)d_in[6];
    const float* b1   = (const float*)d_in[7];
    const float* W2   = (const float*)d_in[8];
    const float* b2   = (const float*)d_in[9];
    float* out = (float*)d_out;
    const int nn = in_sizes[1];

    float *p_bc;
    __nv_bfloat16 *p_x_h, *p_x_l, *p_hdn_h, *p_hdn_l;
    __nv_bfloat16 *p_Wc_h, *p_Wc_l, *p_W1_h, *p_W1_l, *p_W2_h, *p_W2_l;
    cudaGetSymbolAddress((void**)&p_bc,    g_bc);
    cudaGetSymbolAddress((void**)&p_x_h,   g_x_h);
    cudaGetSymbolAddress((void**)&p_x_l,   g_x_l);
    cudaGetSymbolAddress((void**)&p_hdn_h, g_hdn_h);
    cudaGetSymbolAddress((void**)&p_hdn_l, g_hdn_l);
    cudaGetSymbolAddress((void**)&p_Wc_h,  g_Wc_h);
    cudaGetSymbolAddress((void**)&p_Wc_l,  g_Wc_l);
    cudaGetSymbolAddress((void**)&p_W1_h,  g_W1_h);
    cudaGetSymbolAddress((void**)&p_W1_l,  g_W1_l);
    cudaGetSymbolAddress((void**)&p_W2_h,  g_W2_h);
    cudaGetSymbolAddress((void**)&p_W2_l,  g_W2_l);

    cudaFuncSetAttribute(k_gemm,  cudaFuncAttributeMaxDynamicSharedMemorySize, SMEM_BYTES);
    cudaFuncSetAttribute(k_gates, cudaFuncAttributeMaxDynamicSharedMemorySize, G_SMEM_BYTES);

    k_init<<<4096, 256>>>();
    k_prep<<<(GATESD * XDIM) / 256, 256>>>(W_ih, W_hh, b_ih, b_hh);
    k_conv<<<(HIDDEN * XDIM) / 256, 256>>>(W1, p_W1_h, p_W1_l, HIDDEN * XDIM);
    k_conv<<<(HIDDEN * HIDDEN) / 256, 256>>>(W2, p_W2_h, p_W2_l, HIDDEN * HIDDEN);
    k_segments<<<(nn + 255) / 256, 256>>>(bidx, nn);

    for (int s = 0; s < STEPS; s++) {
        k_attention<<<N_GRAPHS, 256>>>(emb);
        k_gates<<<dim3(GATESD / 128, N_GRAPHS / 128), 256, G_SMEM_BYTES>>>(
            p_x_h, p_x_l, p_Wc_h, p_Wc_l, p_bc);
    }

    // MLP readout
    k_gemm<<<dim3(HIDDEN / BN, N_GRAPHS / BM), 256, SMEM_BYTES>>>(
        p_x_h, p_x_l, p_W1_h, p_W1_l, b1, nullptr, p_hdn_h, p_hdn_l,
        HIDDEN, XDIM, 1);
    k_gemm<<<dim3(HIDDEN / BN, N_GRAPHS / BM), 256, SMEM_BYTES>>>(
        p_hdn_h, p_hdn_l, p_W2_h, p_W2_l, b2, out, nullptr, nullptr,
        HIDDEN, HIDDEN, 0);
}

// round 7
// speedup vs baseline: 1.4319x; 1.0160x over previous
#include <cuda_runtime.h>
#include <cuda_bf16.h>
#include <cstdint>
#include <math_constants.h>

#define N_GRAPHS 4096
#define HIDDEN   256
#define STEPS    6
#define GATESD   1024   // 4*HIDDEN
#define XDIM     512    // 2*HIDDEN

// ---------------- scratch (no allocation allowed) ----------------
__device__ float g_h[N_GRAPHS * HIDDEN];
__device__ float g_c[N_GRAPHS * HIDDEN];
__device__ float g_bc[GATESD];                 // b_ih + b_hh, gate-interleaved
__device__ int   g_start[N_GRAPHS];
__device__ int   g_end[N_GRAPHS];
__device__ __nv_bfloat16 g_x_h[N_GRAPHS * XDIM],     g_x_l[N_GRAPHS * XDIM];
__device__ __nv_bfloat16 g_hdn_h[N_GRAPHS * HIDDEN], g_hdn_l[N_GRAPHS * HIDDEN];
__device__ __nv_bfloat16 g_Wc_h[GATESD * XDIM],      g_Wc_l[GATESD * XDIM];   // gate-interleaved rows
__device__ __nv_bfloat16 g_W1_h[HIDDEN * XDIM],      g_W1_l[HIDDEN * XDIM];
__device__ __nv_bfloat16 g_W2_h[HIDDEN * HIDDEN],    g_W2_l[HIDDEN * HIDDEN];

__device__ __forceinline__ void split_bf16(float v, __nv_bfloat16& h, __nv_bfloat16& l) {
    h = __float2bfloat16(v);
    l = __float2bfloat16(v - __bfloat162float(h));
}
__device__ __forceinline__ float sigf(float x) { return 1.f / (1.f + expf(-x)); }

// ---------------- fused setup: init h/c, segments, weight fold+split ----------------
// grid-stride over 524288 "slots"; each slot covers several independent tasks.
__global__ void k_setup(const int* __restrict__ idx, int nn,
                        const float* __restrict__ W_ih, const float* __restrict__ W_hh,
                        const float* __restrict__ b_ih, const float* __restrict__ b_hh,
                        const float* __restrict__ W1, const float* __restrict__ W2) {
    const int i = blockIdx.x * blockDim.x + threadIdx.x;   // 524288 threads

    // zero h, c (1,048,576 each? no — 1,048,576 floats each of h and c)
    g_h[i] = 0.f;              g_h[i + 524288] = 0.f;
    g_c[i] = 0.f;              g_c[i + 524288] = 0.f;
    if (i < N_GRAPHS) { g_start[i] = 0; g_end[i] = 0; }
    __threadfence();   // g_start/g_end zero visible before boundary writes below

    // segment boundaries (batch_indices sorted, int32)
    if (i < nn) {
        const int g = idx[i];
        if ((unsigned)g < (unsigned)N_GRAPHS) {
            if (i == 0      || idx[i - 1] != g) g_start[g] = i;
            if (i == nn - 1 || idx[i + 1] != g) g_end[g]   = i + 1;
        }
    }

    // Wc fold + split (gate-interleaved rows: n' = 4d+gate), 524288 elems
    {
        const int np = i >> 9;
        const int k  = i & 511;
        const int d = np >> 2, gate = np & 3;
        const int orig = gate * HIDDEN + d;
        float v = W_ih[orig * XDIM + k];
        if (k < HIDDEN) v += W_hh[orig * HIDDEN + k];
        split_bf16(v, g_Wc_h[i], g_Wc_l[i]);
    }
    if (i < GATESD) {
        const int d2 = i >> 2, g2 = i & 3;
        const int o2 = g2 * HIDDEN + d2;
        g_bc[i] = b_ih[o2] + b_hh[o2];
    }
    // W1 split (131072), W2 split (65536)
    if (i < HIDDEN * XDIM)   split_bf16(W1[i], g_W1_h[i], g_W1_l[i]);
    if (i < HIDDEN * HIDDEN) split_bf16(W2[i], g_W2_h[i], g_W2_l[i]);
}

// ---------------- single-pass attention, 4 CTAs/SM ----------------
__global__ void __launch_bounds__(256, 4)
k_attention(const float* __restrict__ emb) {
    const int g    = blockIdx.x;
    const int t    = threadIdx.x;
    const int lane = t & 31;
    const int wid  = t >> 5;

    __shared__ float h_s[HIDDEN];
    __shared__ float Rall[8][HIDDEN];
    __shared__ float mw_s[8], Sw_s[8];

    h_s[t] = g_h[(size_t)g * HIDDEN + t];
    const int s  = g_start[g];
    const int en = g_end[g];
    __syncthreads();

    const float4* h4 = reinterpret_cast<const float4*>(h_s);
    const float4 hv0 = h4[lane];
    const float4 hv1 = h4[lane + 32];

    float m = -CUDART_INF_F, S = 0.f;
    float R[8] = {0.f, 0.f, 0.f, 0.f, 0.f, 0.f, 0.f, 0.f};

    int ii = s + wid;
    float4 a0, a1, b0, b1;
    bool h0 = ii < en, h1 = (ii + 8) < en;
    if (h0) {
        const float4* r4 = reinterpret_cast<const float4*>(emb + (size_t)ii * HIDDEN);
        a0 = r4[lane]; a1 = r4[lane + 32];
    }
    if (h1) {
        const float4* r4 = reinterpret_cast<const float4*>(emb + (size_t)(ii + 8) * HIDDEN);
        b0 = r4[lane]; b1 = r4[lane + 32];
    }
    while (h0) {
        const bool h2 = (ii + 16) < en;
        float4 t0, t1;
        if (h2) {
            const float4* r4 = reinterpret_cast<const float4*>(emb + (size_t)(ii + 16) * HIDDEN);
            t0 = r4[lane]; t1 = r4[lane + 32];
        }
        float d = a0.x * hv0.x + a0.y * hv0.y + a0.z * hv0.z + a0.w * hv0.w
                + a1.x * hv1.x + a1.y * hv1.y + a1.z * hv1.z + a1.w * hv1.w;
        #pragma unroll
        for (int o = 16; o > 0; o >>= 1) d += __shfl_xor_sync(0xffffffffu, d, o);
        const float nm = fmaxf(m, d);
        const float sc = __expf(m - nm);
        const float p  = __expf(d - nm);
        S = S * sc + p;
        R[0] = R[0] * sc + p * a0.x;
        R[1] = R[1] * sc + p * a0.y;
        R[2] = R[2] * sc + p * a0.z;
        R[3] = R[3] * sc + p * a0.w;
        R[4] = R[4] * sc + p * a1.x;
        R[5] = R[5] * sc + p * a1.y;
        R[6] = R[6] * sc + p * a1.z;
        R[7] = R[7] * sc + p * a1.w;
        m = nm;
        a0 = b0; a1 = b1;
        b0 = t0; b1 = t1;
        h0 = h1; h1 = h2;
        ii += 8;
    }

    if (lane == 0) { mw_s[wid] = m; Sw_s[wid] = S; }
    #pragma unroll
    for (int j = 0; j < 4; j++) {
        Rall[wid][lane * 4 + j]       = R[j];
        Rall[wid][128 + lane * 4 + j] = R[4 + j];
    }
    __syncthreads();

    float r = 0.f;
    if (en > s) {
        float M = mw_s[0];
        #pragma unroll
        for (int w = 1; w < 8; w++) M = fmaxf(M, mw_s[w]);
        float Ss = 0.f, Rs = 0.f;
        #pragma unroll
        for (int w = 0; w < 8; w++) {
            const float f = __expf(mw_s[w] - M);
            Ss += f * Sw_s[w];
            Rs += f * Rall[w][t];
        }
        r = Rs / (Ss + 1e-16f);
    }

    const size_t xb = (size_t)g * XDIM;
    split_bf16(h_s[t], g_x_h[xb + t],          g_x_l[xb + t]);
    split_bf16(r,      g_x_h[xb + HIDDEN + t], g_x_l[xb + HIDDEN + t]);
}

// ---------------- shared MMA helpers ----------------
__device__ __forceinline__ void mma_bf16(float c[4], const uint32_t a[4], const uint32_t b[2]) {
    asm volatile(
        "mma.sync.aligned.m16n8k16.row.col.f32.bf16.bf16.f32 "
        "{%0,%1,%2,%3}, {%4,%5,%6,%7}, {%8,%9}, {%0,%1,%2,%3};\n"
        : "+f"(c[0]), "+f"(c[1]), "+f"(c[2]), "+f"(c[3])
        : "r"(a[0]), "r"(a[1]), "r"(a[2]), "r"(a[3]), "r"(b[0]), "r"(b[1]));
}
__device__ __forceinline__ void cp16(__nv_bfloat16* dst, const __nv_bfloat16* src) {
    uint32_t d = (uint32_t)__cvta_generic_to_shared(dst);
    asm volatile("cp.async.cg.shared.global [%0], [%1], 16;\n" :: "r"(d), "l"(src));
}

// ======== gates GEMM, single wave: 128x128 tiles, fused LSTM cell ========
#define GP 40
#define GSZ (128 * GP)
#define G_SMEM_BYTES (2 * 4 * GSZ * 2)   // 81920
#define GCP 132

__global__ void __launch_bounds__(256, 2)
k_gates(const __nv_bfloat16* __restrict__ A_h, const __nv_bfloat16* __restrict__ A_l,
        const __nv_bfloat16* __restrict__ B_h, const __nv_bfloat16* __restrict__ B_l,
        const float* __restrict__ bias) {
    extern __shared__ __nv_bfloat16 sg[];
    __shared__ float sbias[128];

    const int tid  = threadIdx.x;
    const int lane = tid & 31;
    const int wid  = tid >> 5;
    const int wm   = wid & 3;
    const int wn   = wid >> 2;
    const int g8   = lane >> 2;
    const int tg   = lane & 3;

    const int m0 = blockIdx.y * 128;
    const int n0 = blockIdx.x * 128;
    const int dbase = n0 >> 2;

    if (tid < 128) sbias[tid] = bias[n0 + tid];

    float acc[2][8][4];
    #pragma unroll
    for (int im = 0; im < 2; im++)
        #pragma unroll
        for (int in = 0; in < 8; in++)
            #pragma unroll
            for (int q = 0; q < 4; q++) acc[im][in][q] = 0.f;

    const int r0 = tid >> 2, q0 = tid & 3;
    const int r1 = (tid + 256) >> 2, q1 = tid & 3;

    auto stage = [&](int t) {
        const int stg = t & 1;
        const int kb = t * 32;
        __nv_bfloat16* base = sg + stg * 4 * GSZ;
        __nv_bfloat16* dAh = base;
        __nv_bfloat16* dAl = base + GSZ;
        __nv_bfloat16* dBh = base + 2 * GSZ;
        __nv_bfloat16* dBl = base + 3 * GSZ;
        cp16(dAh + r0 * GP + q0 * 8, A_h + (size_t)(m0 + r0) * XDIM + kb + q0 * 8);
        cp16(dAh + r1 * GP + q1 * 8, A_h + (size_t)(m0 + r1) * XDIM + kb + q1 * 8);
        cp16(dAl + r0 * GP + q0 * 8, A_l + (size_t)(m0 + r0) * XDIM + kb + q0 * 8);
        cp16(dAl + r1 * GP + q1 * 8, A_l + (size_t)(m0 + r1) * XDIM + kb + q1 * 8);
        cp16(dBh + r0 * GP + q0 * 8, B_h + (size_t)(n0 + r0) * XDIM + kb + q0 * 8);
        cp16(dBh + r1 * GP + q1 * 8, B_h + (size_t)(n0 + r1) * XDIM + kb + q1 * 8);
        cp16(dBl + r0 * GP + q0 * 8, B_l + (size_t)(n0 + r0) * XDIM + kb + q0 * 8);
        cp16(dBl + r1 * GP + q1 * 8, B_l + (size_t)(n0 + r1) * XDIM + kb + q1 * 8);
    };

    stage(0);
    asm volatile("cp.async.commit_group;\n");

    const int T = XDIM / 32;   // 16
    for (int t = 0; t < T; t++) {
        const int stg = t & 1;
        if (t + 1 < T) stage(t + 1);
        asm volatile("cp.async.commit_group;\n");
        asm volatile("cp.async.wait_group 1;\n");
        __syncthreads();

        const __nv_bfloat16* base = sg + stg * 4 * GSZ;
        const __nv_bfloat16* Ah = base;
        const __nv_bfloat16* Al = base + GSZ;
        const __nv_bfloat16* Bh = base + 2 * GSZ;
        const __nv_bfloat16* Bl = base + 3 * GSZ;

        #pragma unroll
        for (int kk = 0; kk < 32; kk += 16) {
            uint32_t ah[2][4], al[2][4];
            #pragma unroll
            for (int im = 0; im < 2; im++) {
                const int r = wm * 32 + im * 16 + g8;
                ah[im][0] = *reinterpret_cast<const uint32_t*>(Ah + r * GP + kk + 2 * tg);
                ah[im][1] = *reinterpret_cast<const uint32_t*>(Ah + (r + 8) * GP + kk + 2 * tg);
                ah[im][2] = *reinterpret_cast<const uint32_t*>(Ah + r * GP + kk + 2 * tg + 8);
                ah[im][3] = *reinterpret_cast<const uint32_t*>(Ah + (r + 8) * GP + kk + 2 * tg + 8);
                al[im][0] = *reinterpret_cast<const uint32_t*>(Al + r * GP + kk + 2 * tg);
                al[im][1] = *reinterpret_cast<const uint32_t*>(Al + (r + 8) * GP + kk + 2 * tg);
                al[im][2] = *reinterpret_cast<const uint32_t*>(Al + r * GP + kk + 2 * tg + 8);
                al[im][3] = *reinterpret_cast<const uint32_t*>(Al + (r + 8) * GP + kk + 2 * tg + 8);
            }
            #pragma unroll
            for (int in = 0; in < 8; in++) {
                const int rn = wn * 64 + in * 8 + g8;
                uint32_t bh[2], bl[2];
                bh[0] = *reinterpret_cast<const uint32_t*>(Bh + rn * GP + kk + 2 * tg);
                bh[1] = *reinterpret_cast<const uint32_t*>(Bh + rn * GP + kk + 2 * tg + 8);
                bl[0] = *reinterpret_cast<const uint32_t*>(Bl + rn * GP + kk + 2 * tg);
                bl[1] = *reinterpret_cast<const uint32_t*>(Bl + rn * GP + kk + 2 * tg + 8);
                #pragma unroll
                for (int im = 0; im < 2; im++) {
                    mma_bf16(acc[im][in], ah[im], bh);
                    mma_bf16(acc[im][in], ah[im], bl);
                    mma_bf16(acc[im][in], al[im], bh);
                }
            }
        }
        __syncthreads();
    }

    // ---- fused LSTM cell epilogue ----
    float* sC = reinterpret_cast<float*>(sg);
    #pragma unroll
    for (int im = 0; im < 2; im++)
        #pragma unroll
        for (int in = 0; in < 8; in++) {
            const int rl = wm * 32 + im * 16 + g8;
            const int cl = wn * 64 + in * 8 + 2 * tg;
            sC[rl * GCP + cl]           = acc[im][in][0] + sbias[cl];
            sC[rl * GCP + cl + 1]       = acc[im][in][1] + sbias[cl + 1];
            sC[(rl + 8) * GCP + cl]     = acc[im][in][2] + sbias[cl];
            sC[(rl + 8) * GCP + cl + 1] = acc[im][in][3] + sbias[cl + 1];
        }
    __syncthreads();

    #pragma unroll
    for (int it = 0; it < 16; it++) {
        const int idx = tid + it * 256;
        const int row = idx >> 5, dl = idx & 31;
        const float4 gv = *reinterpret_cast<const float4*>(&sC[row * GCP + dl * 4]); // i,f,g,o
        const int gi = m0 + row;
        const int d  = dbase + dl;
        const size_t hb = (size_t)gi * HIDDEN + d;
        const float c_old = g_c[hb];
        const float c_new = sigf(gv.y) * c_old + sigf(gv.x) * tanhf(gv.z);
        const float h_new = sigf(gv.w) * tanhf(c_new);
        g_c[hb] = c_new;
        g_h[hb] = h_new;
        split_bf16(h_new, g_x_h[(size_t)gi * XDIM + d], g_x_l[(size_t)gi * XDIM + d]);
    }
}

// ---------------- generic GEMM for the two MLP launches ----------------
#define BM 64
#define BN 128
#define BK 32
#define PITCH 40
#define SZ_A (64 * PITCH)
#define SZ_B (128 * PITCH)
#define SMEM_HALFS (2 * SZ_A * 2 + 2 * SZ_B * 2)
#define SMEM_BYTES (SMEM_HALFS * 2)

__global__ void __launch_bounds__(256, 3)
k_gemm(const __nv_bfloat16* __restrict__ A_h, const __nv_bfloat16* __restrict__ A_l,
       const __nv_bfloat16* __restrict__ B_h, const __nv_bfloat16* __restrict__ B_l,
       const float* __restrict__ bias,
       float* __restrict__ C, __nv_bfloat16* __restrict__ C_h, __nv_bfloat16* __restrict__ C_l,
       int N, int K, int mode) {
    extern __shared__ __nv_bfloat16 sm[];
    __nv_bfloat16* sA_h = sm;
    __nv_bfloat16* sA_l = sA_h + 2 * SZ_A;
    __nv_bfloat16* sB_h = sA_l + 2 * SZ_A;
    __nv_bfloat16* sB_l = sB_h + 2 * SZ_B;

    const int tid  = threadIdx.x;
    const int lane = tid & 31;
    const int wid  = tid >> 5;
    const int wm   = wid & 1;
    const int wn   = wid >> 1;
    const int g8   = lane >> 2;
    const int tg   = lane & 3;

    const int m0 = blockIdx.y * BM;
    const int n0 = blockIdx.x * BN;
    const int T  = K / BK;

    const int ar = tid >> 2, aq = tid & 3;
    const int br0 = tid >> 2, br1 = (tid + 256) >> 2;

    float acc[2][4][4];
    #pragma unroll
    for (int im = 0; im < 2; im++)
        #pragma unroll
        for (int in = 0; in < 4; in++)
            #pragma unroll
            for (int q = 0; q < 4; q++) acc[im][in][q] = 0.f;

    auto stage = [&](int tile, int stg) {
        const int kb = tile * BK;
        __nv_bfloat16* dAh = sA_h + stg * SZ_A;
        __nv_bfloat16* dAl = sA_l + stg * SZ_A;
        __nv_bfloat16* dBh = sB_h + stg * SZ_B;
        __nv_bfloat16* dBl = sB_l + stg * SZ_B;
        cp16(dAh + ar * PITCH + aq * 8, A_h + (size_t)(m0 + ar) * K + kb + aq * 8);
        cp16(dAl + ar * PITCH + aq * 8, A_l + (size_t)(m0 + ar) * K + kb + aq * 8);
        cp16(dBh + br0 * PITCH + aq * 8, B_h + (size_t)(n0 + br0) * K + kb + aq * 8);
        cp16(dBh + br1 * PITCH + aq * 8, B_h + (size_t)(n0 + br1) * K + kb + aq * 8);
        cp16(dBl + br0 * PITCH + aq * 8, B_l + (size_t)(n0 + br0) * K + kb + aq * 8);
        cp16(dBl + br1 * PITCH + aq * 8, B_l + (size_t)(n0 + br1) * K + kb + aq * 8);
    };

    stage(0, 0);
    asm volatile("cp.async.commit_group;\n");

    for (int t = 0; t < T; t++) {
        const int stg = t & 1;
        if (t + 1 < T) stage(t + 1, (t + 1) & 1);
        asm volatile("cp.async.commit_group;\n");
        asm volatile("cp.async.wait_group 1;\n");
        __syncthreads();

        const __nv_bfloat16* Ah = sA_h + stg * SZ_A;
        const __nv_bfloat16* Al = sA_l + stg * SZ_A;
        const __nv_bfloat16* Bh = sB_h + stg * SZ_B;
        const __nv_bfloat16* Bl = sB_l + stg * SZ_B;

        #pragma unroll
        for (int kk = 0; kk < BK; kk += 16) {
            uint32_t ah[2][4], al[2][4], bh[4][2], bl[4][2];
            #pragma unroll
            for (int im = 0; im < 2; im++) {
                const int r = wm * 32 + im * 16 + g8;
                ah[im][0] = *reinterpret_cast<const uint32_t*>(Ah + r * PITCH + kk + 2 * tg);
                ah[im][1] = *reinterpret_cast<const uint32_t*>(Ah + (r + 8) * PITCH + kk + 2 * tg);
                ah[im][2] = *reinterpret_cast<const uint32_t*>(Ah + r * PITCH + kk + 2 * tg + 8);
                ah[im][3] = *reinterpret_cast<const uint32_t*>(Ah + (r + 8) * PITCH + kk + 2 * tg + 8);
                al[im][0] = *reinterpret_cast<const uint32_t*>(Al + r * PITCH + kk + 2 * tg);
                al[im][1] = *reinterpret_cast<const uint32_t*>(Al + (r + 8) * PITCH + kk + 2 * tg);
                al[im][2] = *reinterpret_cast<const uint32_t*>(Al + r * PITCH + kk + 2 * tg + 8);
                al[im][3] = *reinterpret_cast<const uint32_t*>(Al + (r + 8) * PITCH + kk + 2 * tg + 8);
            }
            #pragma unroll
            for (int in = 0; in < 4; in++) {
                const int rn = wn * 32 + in * 8 + g8;
                bh[in][0] = *reinterpret_cast<const uint32_t*>(Bh + rn * PITCH + kk + 2 * tg);
                bh[in][1] = *reinterpret_cast<const uint32_t*>(Bh + rn * PITCH + kk + 2 * tg + 8);
                bl[in][0] = *reinterpret_cast<const uint32_t*>(Bl + rn * PITCH + kk + 2 * tg);
                bl[in][1] = *reinterpret_cast<const uint32_t*>(Bl + rn * PITCH + kk + 2 * tg + 8);
            }
            #pragma unroll
            for (int im = 0; im < 2; im++)
                #pragma unroll
                for (int in = 0; in < 4; in++) {
                    mma_bf16(acc[im][in], ah[im], bh[in]);
                    mma_bf16(acc[im][in], ah[im], bl[in]);
                    mma_bf16(acc[im][in], al[im], bh[in]);
                }
        }
        __syncthreads();
    }

    #pragma unroll
    for (int im = 0; im < 2; im++) {
        #pragma unroll
        for (int in = 0; in < 4; in++) {
            const int row0 = m0 + wm * 32 + im * 16 + g8;
            const int col  = n0 + wn * 32 + in * 8 + 2 * tg;
            const float b0 = bias[col], b1 = bias[col + 1];
            float v0 = acc[im][in][0] + b0;
            float v1 = acc[im][in][1] + b1;
            float v2 = acc[im][in][2] + b0;
            float v3 = acc[im][in][3] + b1;
            if (mode == 1) {
                v0 = fmaxf(v0, 0.f); v1 = fmaxf(v1, 0.f);
                v2 = fmaxf(v2, 0.f); v3 = fmaxf(v3, 0.f);
                __nv_bfloat16 h0, l0, h1, l1;
                split_bf16(v0, h0, l0); split_bf16(v1, h1, l1);
                *reinterpret_cast<__nv_bfloat162*>(&C_h[(size_t)row0 * N + col]) = __nv_bfloat162(h0, h1);
                *reinterpret_cast<__nv_bfloat162*>(&C_l[(size_t)row0 * N + col]) = __nv_bfloat162(l0, l1);
                split_bf16(v2, h0, l0); split_bf16(v3, h1, l1);
                *reinterpret_cast<__nv_bfloat162*>(&C_h[(size_t)(row0 + 8) * N + col]) = __nv_bfloat162(h0, h1);
                *reinterpret_cast<__nv_bfloat162*>(&C_l[(size_t)(row0 + 8) * N + col]) = __nv_bfloat162(l0, l1);
            } else {
                *reinterpret_cast<float2*>(&C[(size_t)row0 * N + col])       = make_float2(v0, v1);
                *reinterpret_cast<float2*>(&C[(size_t)(row0 + 8) * N + col]) = make_float2(v2, v3);
            }
        }
    }
}

// ---------------- launch ----------------
extern "C" void kernel_launch(void* const* d_in, const int* in_sizes, int n_in,
                              void* d_out, int out_size) {
    const float* emb  = (const float*)d_in[0];
    const int*   bidx = (const int*)d_in[1];
    const float* W_ih = (const float*)d_in[2];
    const float* W_hh = (const float*)d_in[3];
    const float* b_ih = (const float*)d_in[4];
    const float* b_hh = (const float*)d_in[5];
    const float* W1   = (const float*)d_in[6];
    const float* b1   = (const float*)d_in[7];
    const float* W2   = (const float*)d_in[8];
    const float* b2   = (const float*)d_in[9];
    float* out = (float*)d_out;
    const int nn = in_sizes[1];

    float *p_bc;
    __nv_bfloat16 *p_x_h, *p_x_l, *p_hdn_h, *p_hdn_l;
    __nv_bfloat16 *p_Wc_h, *p_Wc_l, *p_W1_h, *p_W1_l, *p_W2_h, *p_W2_l;
    cudaGetSymbolAddress((void**)&p_bc,    g_bc);
    cudaGetSymbolAddress((void**)&p_x_h,   g_x_h);
    cudaGetSymbolAddress((void**)&p_x_l,   g_x_l);
    cudaGetSymbolAddress((void**)&p_hdn_h, g_hdn_h);
    cudaGetSymbolAddress((void**)&p_hdn_l, g_hdn_l);
    cudaGetSymbolAddress((void**)&p_Wc_h,  g_Wc_h);
    cudaGetSymbolAddress((void**)&p_Wc_l,  g_Wc_l);
    cudaGetSymbolAddress((void**)&p_W1_h,  g_W1_h);
    cudaGetSymbolAddress((void**)&p_W1_l,  g_W1_l);
    cudaGetSymbolAddress((void**)&p_W2_h,  g_W2_h);
    cudaGetSymbolAddress((void**)&p_W2_l,  g_W2_l);

    cudaFuncSetAttribute(k_gemm,  cudaFuncAttributeMaxDynamicSharedMemorySize, SMEM_BYTES);
    cudaFuncSetAttribute(k_gates, cudaFuncAttributeMaxDynamicSharedMemorySize, G_SMEM_BYTES);

    k_setup<<<2048, 256>>>(bidx, nn, W_ih, W_hh, b_ih, b_hh, W1, W2);

    for (int s = 0; s < STEPS; s++) {
        k_attention<<<N_GRAPHS, 256>>>(emb);
        k_gates<<<dim3(GATESD / 128, N_GRAPHS / 128), 256, G_SMEM_BYTES>>>(
            p_x_h, p_x_l, p_Wc_h, p_Wc_l, p_bc);
    }

    // MLP readout
    k_gemm<<<dim3(HIDDEN / BN, N_GRAPHS / BM), 256, SMEM_BYTES>>>(
        p_x_h, p_x_l, p_W1_h, p_W1_l, b1, nullptr, p_hdn_h, p_hdn_l,
        HIDDEN, XDIM, 1);
    k_gemm<<<dim3(HIDDEN / BN, N_GRAPHS / BM), 256, SMEM_BYTES>>>(
        p_hdn_h, p_hdn_l, p_W2_h, p_W2_l, b2, out, nullptr, nullptr,
        HIDDEN, HIDDEN, 0);
}